// round 4
// baseline (speedup 1.0000x reference)
#include <cuda_runtime.h>
#include <cuda_bf16.h>
#include <cstdint>

// Problem constants
#define BATCH 256
#define EMB   1024
#define SEQ   100           // 10*10
#define NHEAD 16
#define HDIM  64
#define MROWS (BATCH * SEQ) // 25600

// ---------------- scratch (allocation-free: __device__ globals) ----------------
__device__ float g_xflat[(size_t)MROWS * EMB]; // [b*S+s][e]  (x^T + pos)
__device__ float g_q[(size_t)MROWS * EMB];     // [b][h][s][d]
__device__ float g_k[(size_t)MROWS * EMB];     // [b][h][s][d]
__device__ float g_v[(size_t)MROWS * EMB];     // [b][h][s][d]
__device__ float g_att[(size_t)MROWS * EMB];   // [b*S+s][h*64+d]

// ---------------- kernel 1: x [B,E,S] -> xflat [B*S, E], + pos ----------------
__global__ void transpose_pos_kernel(const float* __restrict__ x,
                                     const float* __restrict__ pos,
                                     float* __restrict__ xf) {
    __shared__ float tile[32][33];
    int b  = blockIdx.z;
    int e0 = blockIdx.y * 32;
    int s0 = blockIdx.x * 32;
    int tx = threadIdx.x, ty = threadIdx.y;

    int s = s0 + tx;
    if (s < SEQ)
        tile[ty][tx] = x[(size_t)b * EMB * SEQ + (size_t)(e0 + ty) * SEQ + s];
    __syncthreads();

    int s2 = s0 + ty, e2 = e0 + tx;
    if (s2 < SEQ)
        xf[((size_t)b * SEQ + s2) * EMB + e2] =
            tile[tx][ty] + pos[(size_t)s2 * EMB + e2];
}

// ---------------- kernel 2: SGEMM  C = A[M,K] @ W[K,N] + bias, scatter epilogue
// MODE 0: QKV projection -> write [b, h, s, d]
// MODE 1: O   projection -> write out [b, n, s]   (n = embed channel)
template <int MODE>
__global__ __launch_bounds__(256)
void sgemm_kernel(const float* __restrict__ A, const float* __restrict__ W,
                  const float* __restrict__ bias, float* __restrict__ C) {
    const int K = EMB, N = EMB;
    __shared__ float As[8][128];
    __shared__ float Bs[8][128];

    int tid = threadIdx.x;
    int bm = blockIdx.y * 128;
    int bn = blockIdx.x * 128;

    int a_row = tid >> 1;          // 0..127
    int a_col = (tid & 1) * 4;     // 0 or 4
    int b_row = tid >> 5;          // 0..7
    int b_col = (tid & 31) * 4;    // 0..124

    int ty = tid >> 4;             // 0..15
    int tx = tid & 15;             // 0..15

    float acc[8][8];
#pragma unroll
    for (int i = 0; i < 8; i++)
#pragma unroll
        for (int j = 0; j < 8; j++) acc[i][j] = 0.f;

    const float* Aptr = A + (size_t)(bm + a_row) * K + a_col;
    const float* Wptr = W + (size_t)b_row * N + bn + b_col;

    for (int k0 = 0; k0 < K; k0 += 8) {
        float4 av = *(const float4*)Aptr;
        As[a_col + 0][a_row] = av.x;
        As[a_col + 1][a_row] = av.y;
        As[a_col + 2][a_row] = av.z;
        As[a_col + 3][a_row] = av.w;
        *(float4*)&Bs[b_row][b_col] = *(const float4*)Wptr;
        __syncthreads();

#pragma unroll
        for (int k = 0; k < 8; k++) {
            float4 ra0 = *(const float4*)&As[k][ty * 8];
            float4 ra1 = *(const float4*)&As[k][ty * 8 + 4];
            float4 rb0 = *(const float4*)&Bs[k][tx * 8];
            float4 rb1 = *(const float4*)&Bs[k][tx * 8 + 4];
            float ra[8] = {ra0.x, ra0.y, ra0.z, ra0.w, ra1.x, ra1.y, ra1.z, ra1.w};
            float rb[8] = {rb0.x, rb0.y, rb0.z, rb0.w, rb1.x, rb1.y, rb1.z, rb1.w};
#pragma unroll
            for (int i = 0; i < 8; i++)
#pragma unroll
                for (int j = 0; j < 8; j++)
                    acc[i][j] = fmaf(ra[i], rb[j], acc[i][j]);
        }
        __syncthreads();
        Aptr += 8;
        Wptr += (size_t)8 * N;
    }

#pragma unroll
    for (int i = 0; i < 8; i++) {
        int m = bm + ty * 8 + i;
        int bb = m / SEQ;
        int s  = m % SEQ;
#pragma unroll
        for (int j = 0; j < 8; j++) {
            int n = bn + tx * 8 + j;
            float v = acc[i][j] + bias[n];
            if (MODE == 0) {
                int h = n >> 6, d = n & 63;
                C[(((size_t)bb * NHEAD + h) * SEQ + s) * HDIM + d] = v;
            } else {
                C[((size_t)bb * EMB + n) * SEQ + s] = v;
            }
        }
    }
}

// ---------------- kernel 3: fused attention per (b,h) ----------------
// Q,K,V in [b,h,s,d]; writes attn probs (optional) and attended [b*S+s][h*64+d]
__global__ __launch_bounds__(256)
void attention_kernel(const float* __restrict__ Q, const float* __restrict__ Kg,
                      const float* __restrict__ V, float* __restrict__ att,
                      float* __restrict__ attn_out) {
    extern __shared__ float sm[];
    float* Qs  = sm;            // [100][64]
    float* KsT = Qs + 6400;     // [64][100]  (transposed)
    float* Vs  = KsT + 6400;    // [100][64]
    float* Ps  = Vs + 6400;     // [100][100]

    int bh = blockIdx.x;        // b*16 + h
    int b = bh >> 4, h = bh & 15;
    int tid = threadIdx.x;

    const float* Qg = Q + (size_t)bh * (SEQ * HDIM);
    const float* Kgp = Kg + (size_t)bh * (SEQ * HDIM);
    const float* Vg = V + (size_t)bh * (SEQ * HDIM);

    for (int idx = tid; idx < SEQ * HDIM; idx += 256) {
        int j = idx >> 6, d = idx & 63;
        Qs[idx] = Qg[idx];
        KsT[d * SEQ + j] = Kgp[idx];
        Vs[idx] = Vg[idx];
    }
    __syncthreads();

    // scores = Q K^T / 8
    for (int p = tid; p < SEQ * SEQ; p += 256) {
        int i = p / SEQ, j = p % SEQ;
        float acc = 0.f;
        const float* qr = Qs + i * HDIM;
        const float* kc = KsT + j;
#pragma unroll 16
        for (int d = 0; d < HDIM; d++)
            acc = fmaf(qr[d], kc[d * SEQ], acc);
        Ps[p] = acc * 0.125f;
    }
    __syncthreads();

    // softmax over rows (one warp per row, strided)
    int warp = tid >> 5, lane = tid & 31;
    for (int i = warp; i < SEQ; i += 8) {
        float* row = Ps + i * SEQ;
        float mx = -1e30f;
        for (int j = lane; j < SEQ; j += 32) mx = fmaxf(mx, row[j]);
#pragma unroll
        for (int o = 16; o > 0; o >>= 1) mx = fmaxf(mx, __shfl_xor_sync(0xffffffffu, mx, o));
        float sum = 0.f;
        for (int j = lane; j < SEQ; j += 32) {
            float e = __expf(row[j] - mx);
            row[j] = e;
            sum += e;
        }
#pragma unroll
        for (int o = 16; o > 0; o >>= 1) sum += __shfl_xor_sync(0xffffffffu, sum, o);
        float inv = 1.0f / sum;
        for (int j = lane; j < SEQ; j += 32) row[j] *= inv;
    }
    __syncthreads();

    // attn probs out
    if (attn_out != nullptr) {
        float* dst = attn_out + (size_t)bh * (SEQ * SEQ);
        for (int p = tid; p < SEQ * SEQ; p += 256) dst[p] = Ps[p];
    }

    // attended = P @ V  -> att[b*S+i][h*64+d]
    for (int o = tid; o < SEQ * HDIM; o += 256) {
        int i = o >> 6, d = o & 63;
        float acc = 0.f;
        const float* pr = Ps + i * SEQ;
        const float* vc = Vs + d;
#pragma unroll 20
        for (int j = 0; j < SEQ; j++)
            acc = fmaf(pr[j], vc[j * HDIM], acc);
        att[((size_t)b * SEQ + i) * EMB + h * HDIM + d] = acc;
    }
}

// ---------------- launch ----------------
extern "C" void kernel_launch(void* const* d_in, const int* in_sizes, int n_in,
                              void* d_out, int out_size) {
    const float* x   = (const float*)d_in[0];
    const float* Wq  = (const float*)d_in[1];
    const float* bq  = (const float*)d_in[2];
    const float* Wk  = (const float*)d_in[3];
    const float* bk  = (const float*)d_in[4];
    const float* Wv  = (const float*)d_in[5];
    const float* bv  = (const float*)d_in[6];
    const float* Wo  = (const float*)d_in[7];
    const float* bo  = (const float*)d_in[8];
    const float* pos = (const float*)d_in[9];

    float* out = (float*)d_out;
    const size_t out_elems = (size_t)BATCH * EMB * SEQ;           // 26,214,400
    float* attn_out = ((size_t)out_size > out_elems) ? out + out_elems : nullptr;

    float *xf, *q, *k, *v, *att;
    cudaGetSymbolAddress((void**)&xf,  g_xflat);
    cudaGetSymbolAddress((void**)&q,   g_q);
    cudaGetSymbolAddress((void**)&k,   g_k);
    cudaGetSymbolAddress((void**)&v,   g_v);
    cudaGetSymbolAddress((void**)&att, g_att);

    // 1) transpose + positional encoding
    {
        dim3 grid((SEQ + 31) / 32, EMB / 32, BATCH);
        dim3 blk(32, 32);
        transpose_pos_kernel<<<grid, blk>>>(x, pos, xf);
    }

    // 2) Q/K/V projections
    {
        dim3 grid(EMB / 128, MROWS / 128);
        sgemm_kernel<0><<<grid, 256>>>(xf, Wq, bq, q);
        sgemm_kernel<0><<<grid, 256>>>(xf, Wk, bk, k);
        sgemm_kernel<0><<<grid, 256>>>(xf, Wv, bv, v);
    }

    // 3) attention
    {
        const int smem = (6400 * 3 + SEQ * SEQ) * (int)sizeof(float); // 116800 B
        cudaFuncSetAttribute(attention_kernel,
                             cudaFuncAttributeMaxDynamicSharedMemorySize, smem);
        attention_kernel<<<BATCH * NHEAD, 256, smem>>>(q, k, v, att, attn_out);
    }

    // 4) output projection (+ transpose back to [B, E, H, W])
    {
        dim3 grid(EMB / 128, MROWS / 128);
        sgemm_kernel<1><<<grid, 256>>>(att, Wo, bo, out);
    }
}

// round 6
// speedup vs baseline: 2.2079x; 2.2079x over previous
#include <cuda_runtime.h>
#include <cuda_bf16.h>
#include <cstdint>

// Problem constants
#define BATCH 256
#define EMB   1024
#define SEQ   100
#define NHEAD 16
#define HDIM  64
#define MROWS (BATCH * SEQ)   // 25600

// GEMM tiling
#define BM 128
#define BN 128
#define BK 32
#define STAGES 3
#define GEMM_THREADS 256
// smem: per stage 4 matrices x 128 rows x 40 bf16 (80B padded rows) = 40960B
#define ROW_B     80
#define MAT_BYTES (128 * ROW_B)          // 10240
#define STAGE_BYTES (4 * MAT_BYTES)      // 40960
#define GEMM_SMEM (STAGES * STAGE_BYTES) // 122880

// ---------------- scratch (__device__ globals; no allocation) ----------------
__device__ __nv_bfloat16 g_xf_h[(size_t)MROWS * EMB];
__device__ __nv_bfloat16 g_xf_l[(size_t)MROWS * EMB];
__device__ __nv_bfloat16 g_wt_h[(size_t)4 * EMB * EMB];   // [mat][n][k] = W[k][n]
__device__ __nv_bfloat16 g_wt_l[(size_t)4 * EMB * EMB];
__device__ float         g_q[(size_t)MROWS * EMB];        // [b][h][d][s]
__device__ float         g_k[(size_t)MROWS * EMB];        // [b][h][d][s]
__device__ float         g_v[(size_t)MROWS * EMB];        // [b][h][d][s]
__device__ __nv_bfloat16 g_att_h[(size_t)MROWS * EMB];    // [b*S+s][e]
__device__ __nv_bfloat16 g_att_l[(size_t)MROWS * EMB];

// ---------------- helpers ----------------
__device__ __forceinline__ uint32_t smem_u32(const void* p) {
    return (uint32_t)__cvta_generic_to_shared(p);
}
__device__ __forceinline__ void cp16(uint32_t dst, const void* src) {
    asm volatile("cp.async.cg.shared.global [%0], [%1], 16;" :: "r"(dst), "l"(src));
}
__device__ __forceinline__ void ldmx4(uint32_t addr, uint32_t* r) {
    asm volatile("ldmatrix.sync.aligned.m8n8.x4.shared.b16 {%0,%1,%2,%3}, [%4];"
                 : "=r"(r[0]), "=r"(r[1]), "=r"(r[2]), "=r"(r[3]) : "r"(addr));
}
__device__ __forceinline__ void mma_bf16(float* d, const uint32_t* a, const uint32_t* b) {
    asm volatile(
        "mma.sync.aligned.m16n8k16.row.col.f32.bf16.bf16.f32 "
        "{%0,%1,%2,%3}, {%4,%5,%6,%7}, {%8,%9}, {%0,%1,%2,%3};"
        : "+f"(d[0]), "+f"(d[1]), "+f"(d[2]), "+f"(d[3])
        : "r"(a[0]), "r"(a[1]), "r"(a[2]), "r"(a[3]), "r"(b[0]), "r"(b[1]));
}
__device__ __forceinline__ void bf16_split(float a, __nv_bfloat16& h, __nv_bfloat16& l) {
    h = __float2bfloat16(a);
    l = __float2bfloat16(a - __bfloat162float(h));
}

// ---------------- kernel 1: x [B,E,S] -> xflat hi/lo bf16 [B*S, E], + pos ----
__global__ void transpose_pos_kernel(const float* __restrict__ x,
                                     const float* __restrict__ pos,
                                     __nv_bfloat16* __restrict__ xh,
                                     __nv_bfloat16* __restrict__ xl) {
    __shared__ float tile[32][33];
    int b  = blockIdx.z;
    int e0 = blockIdx.y * 32;
    int s0 = blockIdx.x * 32;
    int tx = threadIdx.x, ty = threadIdx.y;

    int s = s0 + tx;
    if (s < SEQ)
        tile[ty][tx] = x[(size_t)b * EMB * SEQ + (size_t)(e0 + ty) * SEQ + s];
    __syncthreads();

    int s2 = s0 + ty, e2 = e0 + tx;
    if (s2 < SEQ) {
        float v = tile[tx][ty] + pos[(size_t)s2 * EMB + e2];
        __nv_bfloat16 h, l;
        bf16_split(v, h, l);
        size_t o = ((size_t)b * SEQ + s2) * EMB + e2;
        xh[o] = h;
        xl[o] = l;
    }
}

// ---------------- kernel 2: weight transpose + split: W[k][n] -> WT[n][k] ----
__global__ void wconvert_kernel(const float* __restrict__ W,
                                __nv_bfloat16* __restrict__ th,
                                __nv_bfloat16* __restrict__ tl) {
    __shared__ float t[32][33];
    int n0 = blockIdx.x * 32, k0 = blockIdx.y * 32;
    int tx = threadIdx.x, ty = threadIdx.y;
    t[ty][tx] = W[(size_t)(k0 + ty) * EMB + n0 + tx];
    __syncthreads();
    float v = t[tx][ty];                  // = W[k0+tx][n0+ty]
    __nv_bfloat16 h, l;
    bf16_split(v, h, l);
    size_t o = (size_t)(n0 + ty) * EMB + k0 + tx;
    th[o] = h;
    tl[o] = l;
}

// ---------------- kernel 3: HMMA bf16-split GEMM ----------------
// C[M,N] = (Ah+Al)[M,K] @ (Bh+Bl)^T[N,K] + bias
// MODE 0: scatter to [b,h,d,s] (q/k/v).  MODE 1: scatter to out [b,n,s].
__device__ __forceinline__ void load_stage(
    char* sb, const __nv_bfloat16* __restrict__ Ah, const __nv_bfloat16* __restrict__ Al,
    const __nv_bfloat16* __restrict__ Bh, const __nv_bfloat16* __restrict__ Bl,
    int bm, int bn, int k0, int tid) {
    uint32_t sbase = smem_u32(sb);
#pragma unroll
    for (int i = 0; i < 2; i++) {
        int idx = tid + i * GEMM_THREADS;     // 0..511
        int row = idx >> 2, c16 = idx & 3;
        uint32_t dst = sbase + (uint32_t)(row * ROW_B + c16 * 16);
        size_t aoff = (size_t)(bm + row) * EMB + k0 + c16 * 8;
        size_t boff = (size_t)(bn + row) * EMB + k0 + c16 * 8;
        cp16(dst,                 Ah + aoff);
        cp16(dst + MAT_BYTES,     Al + aoff);
        cp16(dst + 2 * MAT_BYTES, Bh + boff);
        cp16(dst + 3 * MAT_BYTES, Bl + boff);
    }
    asm volatile("cp.async.commit_group;" ::: "memory");
}

template <int MODE>
__global__ __launch_bounds__(GEMM_THREADS, 1)
void gemm_tc(const __nv_bfloat16* __restrict__ Ah, const __nv_bfloat16* __restrict__ Al,
             const __nv_bfloat16* __restrict__ Bh, const __nv_bfloat16* __restrict__ Bl,
             const float* __restrict__ bias, float* __restrict__ C) {
    extern __shared__ char dsm[];
    const int tid = threadIdx.x;
    const int lane = tid & 31;
    const int wid = tid >> 5;
    const int warpM = wid & 3;        // 4 warps along M (32 rows each)
    const int warpN = wid >> 2;       // 2 warps along N (64 cols each)
    const int bm = blockIdx.y * BM;
    const int bn = blockIdx.x * BN;

    float acc[2][8][4];
#pragma unroll
    for (int i = 0; i < 2; i++)
#pragma unroll
        for (int j = 0; j < 8; j++)
#pragma unroll
            for (int r = 0; r < 4; r++) acc[i][j][r] = 0.f;

    // prologue: stages 0,1
    load_stage(dsm + 0 * STAGE_BYTES, Ah, Al, Bh, Bl, bm, bn, 0 * BK, tid);
    load_stage(dsm + 1 * STAGE_BYTES, Ah, Al, Bh, Bl, bm, bn, 1 * BK, tid);

    const int NK = EMB / BK;          // 32

    // ldmatrix address components
    const uint32_t a_row = (uint32_t)(warpM * 32 + (lane & 15));
    const uint32_t a_koff = (uint32_t)((lane >> 4) * 16);
    const uint32_t b_row = (uint32_t)(warpN * 64 + (lane & 7) + ((lane >> 4) & 1) * 8);
    const uint32_t b_koff = (uint32_t)(((lane >> 3) & 1) * 16);

    for (int kc = 0; kc < NK; kc++) {
        asm volatile("cp.async.wait_group %0;" :: "n"(STAGES - 2) : "memory");
        __syncthreads();

        if (kc + STAGES - 1 < NK) {
            load_stage(dsm + ((kc + STAGES - 1) % STAGES) * STAGE_BYTES,
                       Ah, Al, Bh, Bl, bm, bn, (kc + STAGES - 1) * BK, tid);
        } else {
            asm volatile("cp.async.commit_group;" ::: "memory");
        }

        uint32_t sb = smem_u32(dsm) + (uint32_t)((kc % STAGES) * STAGE_BYTES);
        uint32_t sAh = sb, sAl = sb + MAT_BYTES;
        uint32_t sBh = sb + 2 * MAT_BYTES, sBl = sb + 3 * MAT_BYTES;

#pragma unroll
        for (int ks = 0; ks < 2; ks++) {
            const uint32_t kb = (uint32_t)(ks * 32);
            uint32_t ah[2][4], al[2][4], bh[4][4], bl[4][4];
#pragma unroll
            for (int mi = 0; mi < 2; mi++) {
                uint32_t ao = (a_row + mi * 16) * ROW_B + kb + a_koff;
                ldmx4(sAh + ao, ah[mi]);
                ldmx4(sAl + ao, al[mi]);
            }
#pragma unroll
            for (int nb = 0; nb < 4; nb++) {
                uint32_t bo = (b_row + nb * 16) * ROW_B + kb + b_koff;
                ldmx4(sBh + bo, bh[nb]);
                ldmx4(sBl + bo, bl[nb]);
            }
#pragma unroll
            for (int mi = 0; mi < 2; mi++)
#pragma unroll
                for (int ni = 0; ni < 8; ni++) {
                    uint32_t* bph = &bh[ni >> 1][(ni & 1) * 2];
                    uint32_t* bpl = &bl[ni >> 1][(ni & 1) * 2];
                    mma_bf16(acc[mi][ni], ah[mi], bph);   // Ah*Bh
                    mma_bf16(acc[mi][ni], ah[mi], bpl);   // Ah*Bl
                    mma_bf16(acc[mi][ni], al[mi], bph);   // Al*Bh
                }
        }
    }

    // epilogue
    const int r0 = lane >> 2;
    const int c0 = (lane & 3) * 2;
#pragma unroll
    for (int mi = 0; mi < 2; mi++) {
        int mbase = bm + warpM * 32 + mi * 16;
#pragma unroll
        for (int ni = 0; ni < 8; ni++) {
            int n = bn + warpN * 64 + ni * 8 + c0;
            float bia0 = bias[n], bia1 = bias[n + 1];
#pragma unroll
            for (int half = 0; half < 2; half++) {   // rows r0 / r0+8
                int m = mbase + r0 + half * 8;
                int bb = m / SEQ, s = m - bb * SEQ;
                float v0 = acc[mi][ni][half * 2 + 0] + bia0;
                float v1 = acc[mi][ni][half * 2 + 1] + bia1;
                if (MODE == 0) {
                    size_t base = (((size_t)bb * NHEAD + (n >> 6)) * HDIM);
                    C[(base + (n & 63)) * SEQ + s] = v0;
                    size_t base1 = (((size_t)bb * NHEAD + ((n + 1) >> 6)) * HDIM);
                    C[(base1 + ((n + 1) & 63)) * SEQ + s] = v1;
                } else {
                    C[((size_t)bb * EMB + n) * SEQ + s] = v0;
                    C[((size_t)bb * EMB + n + 1) * SEQ + s] = v1;
                }
            }
        }
    }
}

// ---------------- kernel 4: fused attention per (b,h) ----------------
// q,k,v in [b,h,d,s]; writes attn probs (optional) and att hi/lo [b*S+s][e]
#define ATT_QS_STRIDE 65
#define ATT_VS_STRIDE 101
#define ATT_SMEM ((SEQ * ATT_QS_STRIDE + HDIM * SEQ + HDIM * ATT_VS_STRIDE + SEQ * SEQ) * 4)
__global__ __launch_bounds__(256)
void attention_kernel(const float* __restrict__ Q, const float* __restrict__ Kg,
                      const float* __restrict__ V,
                      __nv_bfloat16* __restrict__ att_h,
                      __nv_bfloat16* __restrict__ att_l,
                      float* __restrict__ attn_out) {
    extern __shared__ float sm[];
    float* Qs  = sm;                                  // [100][65]
    float* KsT = Qs + SEQ * ATT_QS_STRIDE;            // [64][100]
    float* Vs  = KsT + HDIM * SEQ;                    // [64][101]
    float* Ps  = Vs + HDIM * ATT_VS_STRIDE;           // [100][100]

    int bh = blockIdx.x;
    int b = bh >> 4, h = bh & 15;
    int tid = threadIdx.x;

    const float* Qg = Q + (size_t)bh * (SEQ * HDIM);
    const float* Kp = Kg + (size_t)bh * (SEQ * HDIM);
    const float* Vg = V + (size_t)bh * (SEQ * HDIM);

    for (int idx = tid; idx < SEQ * HDIM; idx += 256) {
        int dd = idx / SEQ, ss = idx - dd * SEQ;      // layout [d][s]
        Qs[ss * ATT_QS_STRIDE + dd] = Qg[idx];
        KsT[idx] = Kp[idx];
        Vs[dd * ATT_VS_STRIDE + ss] = Vg[idx];
    }
    __syncthreads();

    // scores = Q K^T / 8
    for (int p = tid; p < SEQ * SEQ; p += 256) {
        int i = p / SEQ, j = p - (p / SEQ) * SEQ;
        float acc = 0.f;
        const float* qr = Qs + i * ATT_QS_STRIDE;
        const float* kc = KsT + j;
#pragma unroll 16
        for (int d = 0; d < HDIM; d++)
            acc = fmaf(qr[d], kc[d * SEQ], acc);
        Ps[p] = acc * 0.125f;
    }
    __syncthreads();

    // row softmax (one warp per row)
    int warp = tid >> 5, lane = tid & 31;
    for (int i = warp; i < SEQ; i += 8) {
        float* row = Ps + i * SEQ;
        float mx = -1e30f;
        for (int j = lane; j < SEQ; j += 32) mx = fmaxf(mx, row[j]);
#pragma unroll
        for (int o = 16; o > 0; o >>= 1) mx = fmaxf(mx, __shfl_xor_sync(0xffffffffu, mx, o));
        float sum = 0.f;
        for (int j = lane; j < SEQ; j += 32) {
            float e = __expf(row[j] - mx);
            row[j] = e;
            sum += e;
        }
#pragma unroll
        for (int o = 16; o > 0; o >>= 1) sum += __shfl_xor_sync(0xffffffffu, sum, o);
        float inv = 1.0f / sum;
        for (int j = lane; j < SEQ; j += 32) row[j] *= inv;
    }
    __syncthreads();

    if (attn_out != nullptr) {
        float* dst = attn_out + (size_t)bh * (SEQ * SEQ);
        for (int p = tid; p < SEQ * SEQ; p += 256) dst[p] = Ps[p];
    }

    // attended = P @ V -> att[b*S+i][h*64+d], hi/lo split
    for (int o = tid; o < SEQ * HDIM; o += 256) {
        int i = o >> 6, d = o & 63;
        float acc = 0.f;
        const float* pr = Ps + i * SEQ;
        const float* vc = Vs + d * ATT_VS_STRIDE;
#pragma unroll 20
        for (int j = 0; j < SEQ; j++)
            acc = fmaf(pr[j], vc[j], acc);
        __nv_bfloat16 hi, lo;
        bf16_split(acc, hi, lo);
        size_t dst = ((size_t)b * SEQ + i) * EMB + h * HDIM + d;
        att_h[dst] = hi;
        att_l[dst] = lo;
    }
}

// ---------------- launch ----------------
extern "C" void kernel_launch(void* const* d_in, const int* in_sizes, int n_in,
                              void* d_out, int out_size) {
    const float* x   = (const float*)d_in[0];
    const float* Wq  = (const float*)d_in[1];
    const float* bq  = (const float*)d_in[2];
    const float* Wk  = (const float*)d_in[3];
    const float* bk  = (const float*)d_in[4];
    const float* Wv  = (const float*)d_in[5];
    const float* bv  = (const float*)d_in[6];
    const float* Wo  = (const float*)d_in[7];
    const float* bo  = (const float*)d_in[8];
    const float* pos = (const float*)d_in[9];

    float* out = (float*)d_out;
    const size_t out_elems = (size_t)BATCH * EMB * SEQ;
    float* attn_out = ((size_t)out_size > out_elems) ? out + out_elems : nullptr;

    __nv_bfloat16 *xfh, *xfl, *wth, *wtl, *ath, *atl;
    float *q, *k, *v;
    cudaGetSymbolAddress((void**)&xfh, g_xf_h);
    cudaGetSymbolAddress((void**)&xfl, g_xf_l);
    cudaGetSymbolAddress((void**)&wth, g_wt_h);
    cudaGetSymbolAddress((void**)&wtl, g_wt_l);
    cudaGetSymbolAddress((void**)&q,   g_q);
    cudaGetSymbolAddress((void**)&k,   g_k);
    cudaGetSymbolAddress((void**)&v,   g_v);
    cudaGetSymbolAddress((void**)&ath, g_att_h);
    cudaGetSymbolAddress((void**)&atl, g_att_l);

    cudaFuncSetAttribute(gemm_tc<0>, cudaFuncAttributeMaxDynamicSharedMemorySize, GEMM_SMEM);
    cudaFuncSetAttribute(gemm_tc<1>, cudaFuncAttributeMaxDynamicSharedMemorySize, GEMM_SMEM);
    cudaFuncSetAttribute(attention_kernel, cudaFuncAttributeMaxDynamicSharedMemorySize, ATT_SMEM);

    const size_t WSTRIDE = (size_t)EMB * EMB;

    // 1) weight transpose + bf16 split (K-major B operands)
    {
        dim3 grid(EMB / 32, EMB / 32);
        dim3 blk(32, 32);
        wconvert_kernel<<<grid, blk>>>(Wq, wth + 0 * WSTRIDE, wtl + 0 * WSTRIDE);
        wconvert_kernel<<<grid, blk>>>(Wk, wth + 1 * WSTRIDE, wtl + 1 * WSTRIDE);
        wconvert_kernel<<<grid, blk>>>(Wv, wth + 2 * WSTRIDE, wtl + 2 * WSTRIDE);
        wconvert_kernel<<<grid, blk>>>(Wo, wth + 3 * WSTRIDE, wtl + 3 * WSTRIDE);
    }

    // 2) transpose + pos + bf16 split
    {
        dim3 grid((SEQ + 31) / 32, EMB / 32, BATCH);
        dim3 blk(32, 32);
        transpose_pos_kernel<<<grid, blk>>>(x, pos, xfh, xfl);
    }

    // 3) Q/K/V projections (tensor cores via mma.sync)
    {
        dim3 grid(EMB / BN, MROWS / BM);   // (8, 200)
        gemm_tc<0><<<grid, GEMM_THREADS, GEMM_SMEM>>>(xfh, xfl, wth + 0 * WSTRIDE, wtl + 0 * WSTRIDE, bq, q);
        gemm_tc<0><<<grid, GEMM_THREADS, GEMM_SMEM>>>(xfh, xfl, wth + 1 * WSTRIDE, wtl + 1 * WSTRIDE, bk, k);
        gemm_tc<0><<<grid, GEMM_THREADS, GEMM_SMEM>>>(xfh, xfl, wth + 2 * WSTRIDE, wtl + 2 * WSTRIDE, bv, v);
    }

    // 4) attention
    attention_kernel<<<BATCH * NHEAD, 256, ATT_SMEM>>>(q, k, v, ath, atl, attn_out);

    // 5) output projection (+ transpose back to [B, E, H, W])
    {
        dim3 grid(EMB / BN, MROWS / BM);
        gemm_tc<1><<<grid, GEMM_THREADS, GEMM_SMEM>>>(ath, atl, wth + 3 * WSTRIDE, wtl + 3 * WSTRIDE, bo, out);
    }
}

// round 7
// speedup vs baseline: 2.4411x; 1.1056x over previous
#include <cuda_runtime.h>
#include <cuda_bf16.h>
#include <cstdint>

// Problem constants
#define BATCH 256
#define EMB   1024
#define SEQ   100
#define NHEAD 16
#define HDIM  64
#define MROWS (BATCH * SEQ)   // 25600

// GEMM tiling
#define BM 128
#define BN 128
#define BK 32
#define STAGES 3
#define GEMM_THREADS 256
#define ROW_B     80
#define MAT_BYTES (128 * ROW_B)          // 10240
#define STAGE_BYTES (4 * MAT_BYTES)      // 40960
#define GEMM_SMEM (STAGES * STAGE_BYTES) // 122880

// ---------------- scratch (__device__ globals; no allocation) ----------------
__device__ __nv_bfloat16 g_xf_h[(size_t)MROWS * EMB];
__device__ __nv_bfloat16 g_xf_l[(size_t)MROWS * EMB];
__device__ __nv_bfloat16 g_wt_h[(size_t)4 * EMB * EMB];   // [mat][n][k] = W[k][n]
__device__ __nv_bfloat16 g_wt_l[(size_t)4 * EMB * EMB];
__device__ float         g_q[(size_t)MROWS * EMB];        // [b][h][d][s]
__device__ float         g_k[(size_t)MROWS * EMB];        // [b][h][d][s]
__device__ float         g_v[(size_t)MROWS * EMB];        // [b][h][d][s]
__device__ __nv_bfloat16 g_att_h[(size_t)MROWS * EMB];    // [b*S+s][e]
__device__ __nv_bfloat16 g_att_l[(size_t)MROWS * EMB];

// ---------------- helpers ----------------
__device__ __forceinline__ uint32_t smem_u32(const void* p) {
    return (uint32_t)__cvta_generic_to_shared(p);
}
__device__ __forceinline__ void cp16(uint32_t dst, const void* src) {
    asm volatile("cp.async.cg.shared.global [%0], [%1], 16;" :: "r"(dst), "l"(src));
}
__device__ __forceinline__ void ldmx4(uint32_t addr, uint32_t* r) {
    asm volatile("ldmatrix.sync.aligned.m8n8.x4.shared.b16 {%0,%1,%2,%3}, [%4];"
                 : "=r"(r[0]), "=r"(r[1]), "=r"(r[2]), "=r"(r[3]) : "r"(addr));
}
__device__ __forceinline__ void mma_bf16(float* d, const uint32_t* a, const uint32_t* b) {
    asm volatile(
        "mma.sync.aligned.m16n8k16.row.col.f32.bf16.bf16.f32 "
        "{%0,%1,%2,%3}, {%4,%5,%6,%7}, {%8,%9}, {%0,%1,%2,%3};"
        : "+f"(d[0]), "+f"(d[1]), "+f"(d[2]), "+f"(d[3])
        : "r"(a[0]), "r"(a[1]), "r"(a[2]), "r"(a[3]), "r"(b[0]), "r"(b[1]));
}
__device__ __forceinline__ void bf16_split(float a, __nv_bfloat16& h, __nv_bfloat16& l) {
    h = __float2bfloat16(a);
    l = __float2bfloat16(a - __bfloat162float(h));
}

// ---------------- kernel 1: x [B,E,S] -> xflat hi/lo bf16 [B*S, E], + pos ----
__global__ void transpose_pos_kernel(const float* __restrict__ x,
                                     const float* __restrict__ pos,
                                     __nv_bfloat16* __restrict__ xh,
                                     __nv_bfloat16* __restrict__ xl) {
    __shared__ float tile[32][33];
    int b  = blockIdx.z;
    int e0 = blockIdx.y * 32;
    int s0 = blockIdx.x * 32;
    int tx = threadIdx.x, ty = threadIdx.y;

    int s = s0 + tx;
    if (s < SEQ)
        tile[ty][tx] = x[(size_t)b * EMB * SEQ + (size_t)(e0 + ty) * SEQ + s];
    __syncthreads();

    int s2 = s0 + ty, e2 = e0 + tx;
    if (s2 < SEQ) {
        float v = tile[tx][ty] + pos[(size_t)s2 * EMB + e2];
        __nv_bfloat16 h, l;
        bf16_split(v, h, l);
        size_t o = ((size_t)b * SEQ + s2) * EMB + e2;
        xh[o] = h;
        xl[o] = l;
    }
}

// ---------------- kernel 2: weight transpose + split: W[k][n] -> WT[n][k] ----
__global__ void wconvert_kernel(const float* __restrict__ W,
                                __nv_bfloat16* __restrict__ th,
                                __nv_bfloat16* __restrict__ tl) {
    __shared__ float t[32][33];
    int n0 = blockIdx.x * 32, k0 = blockIdx.y * 32;
    int tx = threadIdx.x, ty = threadIdx.y;
    t[ty][tx] = W[(size_t)(k0 + ty) * EMB + n0 + tx];
    __syncthreads();
    float v = t[tx][ty];                  // = W[k0+tx][n0+ty]
    __nv_bfloat16 h, l;
    bf16_split(v, h, l);
    size_t o = (size_t)(n0 + ty) * EMB + k0 + tx;
    th[o] = h;
    tl[o] = l;
}

// ---------------- kernel 3: HMMA bf16-split GEMM ----------------
// C = (Ah+Al)[M,K] @ (Bh+Bl)^T[N,K] + bias
// MODE 0: fused QKV, N = 3072; per-CTA mat select; scatter to [b,h,d,s].
// MODE 1: O projection, N = 1024; scatter to out [b,n,s].
__device__ __forceinline__ void load_stage(
    char* sb, const __nv_bfloat16* __restrict__ Ah, const __nv_bfloat16* __restrict__ Al,
    const __nv_bfloat16* __restrict__ Bh, const __nv_bfloat16* __restrict__ Bl,
    int bm, int bn, int k0, int tid) {
    uint32_t sbase = smem_u32(sb);
#pragma unroll
    for (int i = 0; i < 2; i++) {
        int idx = tid + i * GEMM_THREADS;     // 0..511
        int row = idx >> 2, c16 = idx & 3;
        uint32_t dst = sbase + (uint32_t)(row * ROW_B + c16 * 16);
        size_t aoff = (size_t)(bm + row) * EMB + k0 + c16 * 8;
        size_t boff = (size_t)(bn + row) * EMB + k0 + c16 * 8;
        cp16(dst,                 Ah + aoff);
        cp16(dst + MAT_BYTES,     Al + aoff);
        cp16(dst + 2 * MAT_BYTES, Bh + boff);
        cp16(dst + 3 * MAT_BYTES, Bl + boff);
    }
    asm volatile("cp.async.commit_group;" ::: "memory");
}

template <int MODE>
__global__ __launch_bounds__(GEMM_THREADS, 1)
void gemm_tc(const __nv_bfloat16* __restrict__ Ah, const __nv_bfloat16* __restrict__ Al,
             const __nv_bfloat16* __restrict__ Bh, const __nv_bfloat16* __restrict__ Bl,
             const float* __restrict__ bias0, const float* __restrict__ bias1,
             const float* __restrict__ bias2,
             float* __restrict__ C0, float* __restrict__ C1, float* __restrict__ C2) {
    extern __shared__ char dsm[];
    const int tid = threadIdx.x;
    const int lane = tid & 31;
    const int wid = tid >> 5;
    const int warpM = wid & 3;        // 4 warps along M (32 rows each)
    const int warpN = wid >> 2;       // 2 warps along N (64 cols each)
    const int bm = blockIdx.y * BM;
    const int bn = blockIdx.x * BN;

    // per-CTA output select (BN=128 divides 1024, so mat is uniform per CTA)
    const int mat = bn >> 10;
    float* C = (MODE == 0) ? (mat == 0 ? C0 : (mat == 1 ? C1 : C2)) : C0;
    const float* bias = (MODE == 0) ? (mat == 0 ? bias0 : (mat == 1 ? bias1 : bias2)) : bias0;

    float acc[2][8][4];
#pragma unroll
    for (int i = 0; i < 2; i++)
#pragma unroll
        for (int j = 0; j < 8; j++)
#pragma unroll
            for (int r = 0; r < 4; r++) acc[i][j][r] = 0.f;

    load_stage(dsm + 0 * STAGE_BYTES, Ah, Al, Bh, Bl, bm, bn, 0 * BK, tid);
    load_stage(dsm + 1 * STAGE_BYTES, Ah, Al, Bh, Bl, bm, bn, 1 * BK, tid);

    const int NK = EMB / BK;          // 32

    const uint32_t a_row = (uint32_t)(warpM * 32 + (lane & 15));
    const uint32_t a_koff = (uint32_t)((lane >> 4) * 16);
    const uint32_t b_row = (uint32_t)(warpN * 64 + (lane & 7) + ((lane >> 4) & 1) * 8);
    const uint32_t b_koff = (uint32_t)(((lane >> 3) & 1) * 16);

    for (int kc = 0; kc < NK; kc++) {
        asm volatile("cp.async.wait_group %0;" :: "n"(STAGES - 2) : "memory");
        __syncthreads();

        if (kc + STAGES - 1 < NK) {
            load_stage(dsm + ((kc + STAGES - 1) % STAGES) * STAGE_BYTES,
                       Ah, Al, Bh, Bl, bm, bn, (kc + STAGES - 1) * BK, tid);
        } else {
            asm volatile("cp.async.commit_group;" ::: "memory");
        }

        uint32_t sb = smem_u32(dsm) + (uint32_t)((kc % STAGES) * STAGE_BYTES);
        uint32_t sAh = sb, sAl = sb + MAT_BYTES;
        uint32_t sBh = sb + 2 * MAT_BYTES, sBl = sb + 3 * MAT_BYTES;

#pragma unroll
        for (int ks = 0; ks < 2; ks++) {
            const uint32_t kb = (uint32_t)(ks * 32);
            uint32_t ah[2][4], al[2][4], bh[4][4], bl[4][4];
#pragma unroll
            for (int mi = 0; mi < 2; mi++) {
                uint32_t ao = (a_row + mi * 16) * ROW_B + kb + a_koff;
                ldmx4(sAh + ao, ah[mi]);
                ldmx4(sAl + ao, al[mi]);
            }
#pragma unroll
            for (int nb = 0; nb < 4; nb++) {
                uint32_t bo = (b_row + nb * 16) * ROW_B + kb + b_koff;
                ldmx4(sBh + bo, bh[nb]);
                ldmx4(sBl + bo, bl[nb]);
            }
#pragma unroll
            for (int mi = 0; mi < 2; mi++)
#pragma unroll
                for (int ni = 0; ni < 8; ni++) {
                    uint32_t* bph = &bh[ni >> 1][(ni & 1) * 2];
                    uint32_t* bpl = &bl[ni >> 1][(ni & 1) * 2];
                    mma_bf16(acc[mi][ni], ah[mi], bph);   // Ah*Bh
                    mma_bf16(acc[mi][ni], ah[mi], bpl);   // Ah*Bl
                    mma_bf16(acc[mi][ni], al[mi], bph);   // Al*Bh
                }
        }
    }

    // epilogue
    const int r0 = lane >> 2;
    const int c0 = (lane & 3) * 2;
#pragma unroll
    for (int mi = 0; mi < 2; mi++) {
        int mbase = bm + warpM * 32 + mi * 16;
#pragma unroll
        for (int ni = 0; ni < 8; ni++) {
            int n = bn + warpN * 64 + ni * 8 + c0;
            int nn = n & 1023;
            float bia0 = bias[nn], bia1 = bias[nn + 1];
#pragma unroll
            for (int half = 0; half < 2; half++) {
                int m = mbase + r0 + half * 8;
                int bb = m / SEQ, s = m - bb * SEQ;
                float v0 = acc[mi][ni][half * 2 + 0] + bia0;
                float v1 = acc[mi][ni][half * 2 + 1] + bia1;
                if (MODE == 0) {
                    size_t base0 = (((size_t)bb * NHEAD + (nn >> 6)) * HDIM + (nn & 63));
                    C[base0 * SEQ + s] = v0;
                    size_t base1 = (((size_t)bb * NHEAD + ((nn + 1) >> 6)) * HDIM + ((nn + 1) & 63));
                    C[base1 * SEQ + s] = v1;
                } else {
                    C[((size_t)bb * EMB + n) * SEQ + s] = v0;
                    C[((size_t)bb * EMB + n + 1) * SEQ + s] = v1;
                }
            }
        }
    }
}

// ---------------- kernel 4: register-tiled fused attention per (b,h) -------
// q,k,v in [b,h,d,s]; writes attn probs (optional) and att hi/lo [b*S+s][e]
#define SP 112                 // padded S (16 x 7)
#define VT_STRIDE 101
#define ATT_SMEM ((64 * SP + 64 * SP + 64 * VT_STRIDE + SP * SP) * 4)  // 133376
__global__ __launch_bounds__(256)
void attention_kernel(const float* __restrict__ Q, const float* __restrict__ Kg,
                      const float* __restrict__ V,
                      __nv_bfloat16* __restrict__ att_h,
                      __nv_bfloat16* __restrict__ att_l,
                      float* __restrict__ attn_out) {
    extern __shared__ float sm[];
    float* qT = sm;                         // [64][112]  ([d][s])
    float* kT = qT + 64 * SP;               // [64][112]
    float* vT = kT + 64 * SP;               // [64][101]
    float* Ps = vT + 64 * VT_STRIDE;        // [112][112]

    int bh = blockIdx.x;
    int b = bh >> 4, h = bh & 15;
    int tid = threadIdx.x;

    const float* Qg = Q + (size_t)bh * (SEQ * HDIM);
    const float* Kp = Kg + (size_t)bh * (SEQ * HDIM);
    const float* Vg = V + (size_t)bh * (SEQ * HDIM);

    for (int idx = tid; idx < 64 * SP; idx += 256) {
        int d = idx / SP, s = idx - d * SP;
        float qv = 0.f, kv = 0.f;
        if (s < SEQ) { qv = Qg[d * SEQ + s]; kv = Kp[d * SEQ + s]; }
        qT[idx] = qv;
        kT[idx] = kv;
    }
    for (int idx = tid; idx < 64 * VT_STRIDE; idx += 256) {
        int d = idx / VT_STRIDE, s = idx - d * VT_STRIDE;
        vT[idx] = (s < SEQ) ? Vg[d * SEQ + s] : 0.f;
    }
    __syncthreads();

    const int ti = tid >> 4, tj = tid & 15;
    const int i0 = ti * 7, j0 = tj * 7;

    // ---- scores = Q K^T / 8 (7x7 register tile per thread) ----
    {
        float acc[7][7];
#pragma unroll
        for (int a = 0; a < 7; a++)
#pragma unroll
            for (int bq = 0; bq < 7; bq++) acc[a][bq] = 0.f;

        for (int d = 0; d < HDIM; d++) {
            float qv[7], kv[7];
#pragma unroll
            for (int a = 0; a < 7; a++) qv[a] = qT[d * SP + i0 + a];
#pragma unroll
            for (int bq = 0; bq < 7; bq++) kv[bq] = kT[d * SP + j0 + bq];
#pragma unroll
            for (int a = 0; a < 7; a++)
#pragma unroll
                for (int bq = 0; bq < 7; bq++)
                    acc[a][bq] = fmaf(qv[a], kv[bq], acc[a][bq]);
        }
#pragma unroll
        for (int a = 0; a < 7; a++) {
            int i = i0 + a;
#pragma unroll
            for (int bq = 0; bq < 7; bq++) {
                int j = j0 + bq;
                Ps[i * SP + j] = (j < SEQ) ? acc[a][bq] * 0.125f : -1e30f;
            }
        }
    }
    __syncthreads();

    // ---- row softmax (one warp per row) ----
    {
        int warp = tid >> 5, lane = tid & 31;
        for (int i = warp; i < SEQ; i += 8) {
            float* row = Ps + i * SP;
            float mx = -1e30f;
            for (int j = lane; j < SP; j += 32) mx = fmaxf(mx, row[j]);
#pragma unroll
            for (int o = 16; o > 0; o >>= 1) mx = fmaxf(mx, __shfl_xor_sync(0xffffffffu, mx, o));
            float sum = 0.f;
            for (int j = lane; j < SP; j += 32) {
                float e = __expf(row[j] - mx);
                row[j] = e;
                sum += e;
            }
#pragma unroll
            for (int o = 16; o > 0; o >>= 1) sum += __shfl_xor_sync(0xffffffffu, sum, o);
            float inv = 1.0f / sum;
            for (int j = lane; j < SP; j += 32) row[j] *= inv;
        }
    }
    __syncthreads();

    if (attn_out != nullptr) {
        float* dst = attn_out + (size_t)bh * (SEQ * SEQ);
        for (int p = tid; p < SEQ * SEQ; p += 256) {
            int i = p / SEQ, j = p - (p / SEQ) * SEQ;
            dst[p] = Ps[i * SP + j];
        }
    }

    // ---- attended = P @ V (7x4 register tile; dd = tj + 16c, conflict-free) --
    {
        float pacc[7][4];
#pragma unroll
        for (int a = 0; a < 7; a++)
#pragma unroll
            for (int c = 0; c < 4; c++) pacc[a][c] = 0.f;

        for (int j = 0; j < SEQ; j++) {
            float pv[7], vv[4];
#pragma unroll
            for (int a = 0; a < 7; a++) pv[a] = Ps[(i0 + a) * SP + j];
#pragma unroll
            for (int c = 0; c < 4; c++) vv[c] = vT[(tj + c * 16) * VT_STRIDE + j];
#pragma unroll
            for (int a = 0; a < 7; a++)
#pragma unroll
                for (int c = 0; c < 4; c++)
                    pacc[a][c] = fmaf(pv[a], vv[c], pacc[a][c]);
        }
#pragma unroll
        for (int a = 0; a < 7; a++) {
            int i = i0 + a;
            if (i >= SEQ) continue;
#pragma unroll
            for (int c = 0; c < 4; c++) {
                int dd = tj + c * 16;
                __nv_bfloat16 hi, lo;
                bf16_split(pacc[a][c], hi, lo);
                size_t dst = ((size_t)b * SEQ + i) * EMB + h * HDIM + dd;
                att_h[dst] = hi;
                att_l[dst] = lo;
            }
        }
    }
}

// ---------------- launch ----------------
extern "C" void kernel_launch(void* const* d_in, const int* in_sizes, int n_in,
                              void* d_out, int out_size) {
    const float* x   = (const float*)d_in[0];
    const float* Wq  = (const float*)d_in[1];
    const float* bq  = (const float*)d_in[2];
    const float* Wk  = (const float*)d_in[3];
    const float* bk  = (const float*)d_in[4];
    const float* Wv  = (const float*)d_in[5];
    const float* bv  = (const float*)d_in[6];
    const float* Wo  = (const float*)d_in[7];
    const float* bo  = (const float*)d_in[8];
    const float* pos = (const float*)d_in[9];

    float* out = (float*)d_out;
    const size_t out_elems = (size_t)BATCH * EMB * SEQ;
    float* attn_out = ((size_t)out_size > out_elems) ? out + out_elems : nullptr;

    __nv_bfloat16 *xfh, *xfl, *wth, *wtl, *ath, *atl;
    float *q, *k, *v;
    cudaGetSymbolAddress((void**)&xfh, g_xf_h);
    cudaGetSymbolAddress((void**)&xfl, g_xf_l);
    cudaGetSymbolAddress((void**)&wth, g_wt_h);
    cudaGetSymbolAddress((void**)&wtl, g_wt_l);
    cudaGetSymbolAddress((void**)&q,   g_q);
    cudaGetSymbolAddress((void**)&k,   g_k);
    cudaGetSymbolAddress((void**)&v,   g_v);
    cudaGetSymbolAddress((void**)&ath, g_att_h);
    cudaGetSymbolAddress((void**)&atl, g_att_l);

    cudaFuncSetAttribute(gemm_tc<0>, cudaFuncAttributeMaxDynamicSharedMemorySize, GEMM_SMEM);
    cudaFuncSetAttribute(gemm_tc<1>, cudaFuncAttributeMaxDynamicSharedMemorySize, GEMM_SMEM);
    cudaFuncSetAttribute(attention_kernel, cudaFuncAttributeMaxDynamicSharedMemorySize, ATT_SMEM);

    const size_t WSTRIDE = (size_t)EMB * EMB;

    // 1) weight transpose + bf16 split (K-major B operands)
    {
        dim3 grid(EMB / 32, EMB / 32);
        dim3 blk(32, 32);
        wconvert_kernel<<<grid, blk>>>(Wq, wth + 0 * WSTRIDE, wtl + 0 * WSTRIDE);
        wconvert_kernel<<<grid, blk>>>(Wk, wth + 1 * WSTRIDE, wtl + 1 * WSTRIDE);
        wconvert_kernel<<<grid, blk>>>(Wv, wth + 2 * WSTRIDE, wtl + 2 * WSTRIDE);
        wconvert_kernel<<<grid, blk>>>(Wo, wth + 3 * WSTRIDE, wtl + 3 * WSTRIDE);
    }

    // 2) transpose + pos + bf16 split
    {
        dim3 grid((SEQ + 31) / 32, EMB / 32, BATCH);
        dim3 blk(32, 32);
        transpose_pos_kernel<<<grid, blk>>>(x, pos, xfh, xfl);
    }

    // 3) fused Q/K/V projection (one GEMM over N=3072)
    {
        dim3 grid(3 * EMB / BN, MROWS / BM);   // (24, 200)
        gemm_tc<0><<<grid, GEMM_THREADS, GEMM_SMEM>>>(
            xfh, xfl, wth, wtl, bq, bk, bv, q, k, v);
    }

    // 4) attention
    attention_kernel<<<BATCH * NHEAD, 256, ATT_SMEM>>>(q, k, v, ath, atl, attn_out);

    // 5) output projection (+ transpose back to [B, E, H, W])
    {
        dim3 grid(EMB / BN, MROWS / BM);
        gemm_tc<1><<<grid, GEMM_THREADS, GEMM_SMEM>>>(
            ath, atl, wth + 3 * WSTRIDE, wtl + 3 * WSTRIDE, bo, nullptr, nullptr,
            out, nullptr, nullptr);
    }
}

// round 10
// speedup vs baseline: 4.1213x; 1.6883x over previous
#include <cuda_runtime.h>
#include <cuda_fp16.h>
#include <cstdint>

// Problem constants
#define BATCH 256
#define EMB   1024
#define SEQ   100
#define NHEAD 16
#define HDIM  64
#define MROWS (BATCH * SEQ)   // 25600

// GEMM tiling
#define BM 128
#define BN 128
#define BK 32
#define STAGES 3
#define GEMM_THREADS 256
#define ROW_B     80
#define MAT_BYTES (128 * ROW_B)          // 10240
#define STAGE_BYTES (2 * MAT_BYTES)      // 20480 (A + B, fp16 single)
#define GEMM_SMEM (STAGES * STAGE_BYTES) // 61440

// ---------------- scratch (__device__ globals; no allocation) ----------------
__device__ __half g_xf[(size_t)MROWS * EMB];          // [b*S+s][e]
__device__ __half g_wt[(size_t)4 * EMB * EMB];        // [mat][n][k] = W[k][n]
__device__ float  g_q[(size_t)MROWS * EMB];           // [b][h][d][s]
__device__ float  g_k[(size_t)MROWS * EMB];           // [b][h][d][s]
__device__ float  g_v[(size_t)MROWS * EMB];           // [b][h][d][s]
__device__ __half g_att[(size_t)MROWS * EMB];         // [b*S+s][e]

// ---------------- helpers ----------------
__device__ __forceinline__ uint32_t smem_u32(const void* p) {
    return (uint32_t)__cvta_generic_to_shared(p);
}
__device__ __forceinline__ void cp16(uint32_t dst, const void* src) {
    asm volatile("cp.async.cg.shared.global [%0], [%1], 16;" :: "r"(dst), "l"(src));
}
__device__ __forceinline__ void ldmx4(uint32_t addr, uint32_t* r) {
    asm volatile("ldmatrix.sync.aligned.m8n8.x4.shared.b16 {%0,%1,%2,%3}, [%4];"
                 : "=r"(r[0]), "=r"(r[1]), "=r"(r[2]), "=r"(r[3]) : "r"(addr));
}
__device__ __forceinline__ void mma_fp16(float* d, const uint32_t* a, const uint32_t* b) {
    asm volatile(
        "mma.sync.aligned.m16n8k16.row.col.f32.f16.f16.f32 "
        "{%0,%1,%2,%3}, {%4,%5,%6,%7}, {%8,%9}, {%0,%1,%2,%3};"
        : "+f"(d[0]), "+f"(d[1]), "+f"(d[2]), "+f"(d[3])
        : "r"(a[0]), "r"(a[1]), "r"(a[2]), "r"(a[3]), "r"(b[0]), "r"(b[1]));
}

// ---------------- kernel 1: x [B,E,S] -> xflat fp16 [B*S, E], + pos ----------
__global__ void transpose_pos_kernel(const float* __restrict__ x,
                                     const float* __restrict__ pos,
                                     __half* __restrict__ xf) {
    __shared__ float tile[32][33];
    int b  = blockIdx.z;
    int e0 = blockIdx.y * 32;
    int s0 = blockIdx.x * 32;
    int tx = threadIdx.x, ty = threadIdx.y;

    int s = s0 + tx;
    if (s < SEQ)
        tile[ty][tx] = x[(size_t)b * EMB * SEQ + (size_t)(e0 + ty) * SEQ + s];
    __syncthreads();

    int s2 = s0 + ty, e2 = e0 + tx;
    if (s2 < SEQ) {
        float v = tile[tx][ty] + pos[(size_t)s2 * EMB + e2];
        xf[((size_t)b * SEQ + s2) * EMB + e2] = __float2half(v);
    }
}

// ---------------- kernel 2: weight transpose: W[k][n] -> WT[n][k] fp16 ------
__global__ void wconvert_kernel(const float* __restrict__ W,
                                __half* __restrict__ t_out) {
    __shared__ float t[32][33];
    int n0 = blockIdx.x * 32, k0 = blockIdx.y * 32;
    int tx = threadIdx.x, ty = threadIdx.y;
    t[ty][tx] = W[(size_t)(k0 + ty) * EMB + n0 + tx];
    __syncthreads();
    t_out[(size_t)(n0 + ty) * EMB + k0 + tx] = __float2half(t[tx][ty]);
}

// ---------------- kernel 3: fp16 HMMA GEMM ----------------
// C = A[M,K] @ B^T[N,K] + bias
// MODE 0: fused QKV, N = 3072; per-CTA mat select; scatter to [b,h,d,s].
// MODE 1: O projection, N = 1024; scatter to out [b,n,s].
__device__ __forceinline__ void load_stage(
    char* sb, const __half* __restrict__ A, const __half* __restrict__ B,
    int bm, int bn, int k0, int tid) {
    uint32_t sbase = smem_u32(sb);
#pragma unroll
    for (int i = 0; i < 2; i++) {
        int idx = tid + i * GEMM_THREADS;     // 0..511
        int row = idx >> 2, c16 = idx & 3;
        uint32_t dst = sbase + (uint32_t)(row * ROW_B + c16 * 16);
        cp16(dst,             A + (size_t)(bm + row) * EMB + k0 + c16 * 8);
        cp16(dst + MAT_BYTES, B + (size_t)(bn + row) * EMB + k0 + c16 * 8);
    }
    asm volatile("cp.async.commit_group;" ::: "memory");
}

template <int MODE>
__global__ __launch_bounds__(GEMM_THREADS, 2)
void gemm_tc(const __half* __restrict__ A, const __half* __restrict__ B,
             const float* __restrict__ bias0, const float* __restrict__ bias1,
             const float* __restrict__ bias2,
             float* __restrict__ C0, float* __restrict__ C1, float* __restrict__ C2) {
    extern __shared__ char dsm[];
    const int tid = threadIdx.x;
    const int lane = tid & 31;
    const int wid = tid >> 5;
    const int warpM = wid & 3;        // 4 warps along M (32 rows each)
    const int warpN = wid >> 2;       // 2 warps along N (64 cols each)
    const int bm = blockIdx.y * BM;
    const int bn = blockIdx.x * BN;

    const int mat = bn >> 10;
    float* C = (MODE == 0) ? (mat == 0 ? C0 : (mat == 1 ? C1 : C2)) : C0;
    const float* bias = (MODE == 0) ? (mat == 0 ? bias0 : (mat == 1 ? bias1 : bias2)) : bias0;

    float acc[2][8][4];
#pragma unroll
    for (int i = 0; i < 2; i++)
#pragma unroll
        for (int j = 0; j < 8; j++)
#pragma unroll
            for (int r = 0; r < 4; r++) acc[i][j][r] = 0.f;

    load_stage(dsm + 0 * STAGE_BYTES, A, B, bm, bn, 0 * BK, tid);
    load_stage(dsm + 1 * STAGE_BYTES, A, B, bm, bn, 1 * BK, tid);

    const int NK = EMB / BK;          // 32

    const uint32_t a_row = (uint32_t)(warpM * 32 + (lane & 15));
    const uint32_t a_koff = (uint32_t)((lane >> 4) * 16);
    const uint32_t b_row = (uint32_t)(warpN * 64 + (lane & 7) + ((lane >> 4) & 1) * 8);
    const uint32_t b_koff = (uint32_t)(((lane >> 3) & 1) * 16);

    for (int kc = 0; kc < NK; kc++) {
        asm volatile("cp.async.wait_group %0;" :: "n"(STAGES - 2) : "memory");
        __syncthreads();

        if (kc + STAGES - 1 < NK) {
            load_stage(dsm + ((kc + STAGES - 1) % STAGES) * STAGE_BYTES,
                       A, B, bm, bn, (kc + STAGES - 1) * BK, tid);
        } else {
            asm volatile("cp.async.commit_group;" ::: "memory");
        }

        uint32_t sb = smem_u32(dsm) + (uint32_t)((kc % STAGES) * STAGE_BYTES);
        uint32_t sA = sb, sB = sb + MAT_BYTES;

#pragma unroll
        for (int ks = 0; ks < 2; ks++) {
            const uint32_t kb = (uint32_t)(ks * 32);
            uint32_t af[2][4], bf[4][4];
#pragma unroll
            for (int mi = 0; mi < 2; mi++)
                ldmx4(sA + (a_row + mi * 16) * ROW_B + kb + a_koff, af[mi]);
#pragma unroll
            for (int nb = 0; nb < 4; nb++)
                ldmx4(sB + (b_row + nb * 16) * ROW_B + kb + b_koff, bf[nb]);
#pragma unroll
            for (int mi = 0; mi < 2; mi++)
#pragma unroll
                for (int ni = 0; ni < 8; ni++)
                    mma_fp16(acc[mi][ni], af[mi], &bf[ni >> 1][(ni & 1) * 2]);
        }
    }

    // epilogue
    const int r0 = lane >> 2;
    const int c0 = (lane & 3) * 2;
#pragma unroll
    for (int mi = 0; mi < 2; mi++) {
        int mbase = bm + warpM * 32 + mi * 16;
#pragma unroll
        for (int ni = 0; ni < 8; ni++) {
            int n = bn + warpN * 64 + ni * 8 + c0;
            int nn = n & 1023;
            float bia0 = bias[nn], bia1 = bias[nn + 1];
#pragma unroll
            for (int half = 0; half < 2; half++) {
                int m = mbase + r0 + half * 8;
                int bb = m / SEQ, s = m - bb * SEQ;
                float v0 = acc[mi][ni][half * 2 + 0] + bia0;
                float v1 = acc[mi][ni][half * 2 + 1] + bia1;
                if (MODE == 0) {
                    size_t base0 = (((size_t)bb * NHEAD + (nn >> 6)) * HDIM + (nn & 63));
                    C[base0 * SEQ + s] = v0;
                    size_t base1 = (((size_t)bb * NHEAD + ((nn + 1) >> 6)) * HDIM + ((nn + 1) & 63));
                    C[base1 * SEQ + s] = v1;
                } else {
                    C[((size_t)bb * EMB + n) * SEQ + s] = v0;
                    C[((size_t)bb * EMB + n + 1) * SEQ + s] = v1;
                }
            }
        }
    }
}

// ---------------- kernel 4: register-tiled fused attention per (b,h) -------
// q,k,v in [b,h,d,s]; writes attn probs (optional) and att fp16 [b*S+s][e]
#define SP 112                 // padded S (16 x 7)
#define VT_STRIDE 101
#define ATT_SMEM ((64 * SP + 64 * SP + 64 * VT_STRIDE + SP * SP) * 4)  // 133376
__global__ __launch_bounds__(256)
void attention_kernel(const float* __restrict__ Q, const float* __restrict__ Kg,
                      const float* __restrict__ V,
                      __half* __restrict__ att,
                      float* __restrict__ attn_out) {
    extern __shared__ float sm[];
    float* qT = sm;                         // [64][112]  ([d][s])
    float* kT = qT + 64 * SP;               // [64][112]
    float* vT = kT + 64 * SP;               // [64][101]
    float* Ps = vT + 64 * VT_STRIDE;        // [112][112]

    int bh = blockIdx.x;
    int b = bh >> 4, h = bh & 15;
    int tid = threadIdx.x;

    const float* Qg = Q + (size_t)bh * (SEQ * HDIM);
    const float* Kp = Kg + (size_t)bh * (SEQ * HDIM);
    const float* Vg = V + (size_t)bh * (SEQ * HDIM);

    for (int idx = tid; idx < 64 * SP; idx += 256) {
        int d = idx / SP, s = idx - d * SP;
        float qv = 0.f, kv = 0.f;
        if (s < SEQ) { qv = Qg[d * SEQ + s]; kv = Kp[d * SEQ + s]; }
        qT[idx] = qv;
        kT[idx] = kv;
    }
    for (int idx = tid; idx < 64 * VT_STRIDE; idx += 256) {
        int d = idx / VT_STRIDE, s = idx - d * VT_STRIDE;
        vT[idx] = (s < SEQ) ? Vg[d * SEQ + s] : 0.f;
    }
    __syncthreads();

    const int ti = tid >> 4, tj = tid & 15;
    const int i0 = ti * 7, j0 = tj * 7;

    // ---- scores = Q K^T / 8 (7x7 register tile per thread) ----
    {
        float acc[7][7];
#pragma unroll
        for (int a = 0; a < 7; a++)
#pragma unroll
            for (int bq = 0; bq < 7; bq++) acc[a][bq] = 0.f;

        for (int d = 0; d < HDIM; d++) {
            float qv[7], kv[7];
#pragma unroll
            for (int a = 0; a < 7; a++) qv[a] = qT[d * SP + i0 + a];
#pragma unroll
            for (int bq = 0; bq < 7; bq++) kv[bq] = kT[d * SP + j0 + bq];
#pragma unroll
            for (int a = 0; a < 7; a++)
#pragma unroll
                for (int bq = 0; bq < 7; bq++)
                    acc[a][bq] = fmaf(qv[a], kv[bq], acc[a][bq]);
        }
#pragma unroll
        for (int a = 0; a < 7; a++) {
            int i = i0 + a;
#pragma unroll
            for (int bq = 0; bq < 7; bq++) {
                int j = j0 + bq;
                Ps[i * SP + j] = (j < SEQ) ? acc[a][bq] * 0.125f : -1e30f;
            }
        }
    }
    __syncthreads();

    // ---- row softmax (one warp per row) ----
    {
        int warp = tid >> 5, lane = tid & 31;
        for (int i = warp; i < SEQ; i += 8) {
            float* row = Ps + i * SP;
            float mx = -1e30f;
            for (int j = lane; j < SP; j += 32) mx = fmaxf(mx, row[j]);
#pragma unroll
            for (int o = 16; o > 0; o >>= 1) mx = fmaxf(mx, __shfl_xor_sync(0xffffffffu, mx, o));
            float sum = 0.f;
            for (int j = lane; j < SP; j += 32) {
                float e = __expf(row[j] - mx);
                row[j] = e;
                sum += e;
            }
#pragma unroll
            for (int o = 16; o > 0; o >>= 1) sum += __shfl_xor_sync(0xffffffffu, sum, o);
            float inv = 1.0f / sum;
            for (int j = lane; j < SP; j += 32) row[j] *= inv;
        }
    }
    __syncthreads();

    if (attn_out != nullptr) {
        float* dst = attn_out + (size_t)bh * (SEQ * SEQ);
        for (int p = tid; p < SEQ * SEQ; p += 256) {
            int i = p / SEQ, j = p - (p / SEQ) * SEQ;
            dst[p] = Ps[i * SP + j];
        }
    }

    // ---- attended = P @ V (7x4 register tile; dd = tj + 16c, conflict-free) --
    {
        float pacc[7][4];
#pragma unroll
        for (int a = 0; a < 7; a++)
#pragma unroll
            for (int c = 0; c < 4; c++) pacc[a][c] = 0.f;

        for (int j = 0; j < SEQ; j++) {
            float pv[7], vv[4];
#pragma unroll
            for (int a = 0; a < 7; a++) pv[a] = Ps[(i0 + a) * SP + j];
#pragma unroll
            for (int c = 0; c < 4; c++) vv[c] = vT[(tj + c * 16) * VT_STRIDE + j];
#pragma unroll
            for (int a = 0; a < 7; a++)
#pragma unroll
                for (int c = 0; c < 4; c++)
                    pacc[a][c] = fmaf(pv[a], vv[c], pacc[a][c]);
        }
#pragma unroll
        for (int a = 0; a < 7; a++) {
            int i = i0 + a;
            if (i >= SEQ) continue;
#pragma unroll
            for (int c = 0; c < 4; c++) {
                int dd = tj + c * 16;
                size_t dst = ((size_t)b * SEQ + i) * EMB + h * HDIM + dd;
                att[dst] = __float2half(pacc[a][c]);
            }
        }
    }
}

// ---------------- launch ----------------
extern "C" void kernel_launch(void* const* d_in, const int* in_sizes, int n_in,
                              void* d_out, int out_size) {
    const float* x   = (const float*)d_in[0];
    const float* Wq  = (const float*)d_in[1];
    const float* bq  = (const float*)d_in[2];
    const float* Wk  = (const float*)d_in[3];
    const float* bk  = (const float*)d_in[4];
    const float* Wv  = (const float*)d_in[5];
    const float* bv  = (const float*)d_in[6];
    const float* Wo  = (const float*)d_in[7];
    const float* bo  = (const float*)d_in[8];
    const float* pos = (const float*)d_in[9];

    float* out = (float*)d_out;
    const size_t out_elems = (size_t)BATCH * EMB * SEQ;
    float* attn_out = ((size_t)out_size > out_elems) ? out + out_elems : nullptr;

    __half *xf, *wt, *att;
    float *q, *k, *v;
    cudaGetSymbolAddress((void**)&xf,  g_xf);
    cudaGetSymbolAddress((void**)&wt,  g_wt);
    cudaGetSymbolAddress((void**)&q,   g_q);
    cudaGetSymbolAddress((void**)&k,   g_k);
    cudaGetSymbolAddress((void**)&v,   g_v);
    cudaGetSymbolAddress((void**)&att, g_att);

    cudaFuncSetAttribute(gemm_tc<0>, cudaFuncAttributeMaxDynamicSharedMemorySize, GEMM_SMEM);
    cudaFuncSetAttribute(gemm_tc<1>, cudaFuncAttributeMaxDynamicSharedMemorySize, GEMM_SMEM);
    cudaFuncSetAttribute(attention_kernel, cudaFuncAttributeMaxDynamicSharedMemorySize, ATT_SMEM);

    const size_t WSTRIDE = (size_t)EMB * EMB;

    // 1) weight transpose to K-major fp16
    {
        dim3 grid(EMB / 32, EMB / 32);
        dim3 blk(32, 32);
        wconvert_kernel<<<grid, blk>>>(Wq, wt + 0 * WSTRIDE);
        wconvert_kernel<<<grid, blk>>>(Wk, wt + 1 * WSTRIDE);
        wconvert_kernel<<<grid, blk>>>(Wv, wt + 2 * WSTRIDE);
        wconvert_kernel<<<grid, blk>>>(Wo, wt + 3 * WSTRIDE);
    }

    // 2) transpose + pos -> fp16
    {
        dim3 grid((SEQ + 31) / 32, EMB / 32, BATCH);
        dim3 blk(32, 32);
        transpose_pos_kernel<<<grid, blk>>>(x, pos, xf);
    }

    // 3) fused Q/K/V projection (one GEMM over N=3072)
    {
        dim3 grid(3 * EMB / BN, MROWS / BM);   // (24, 200)
        gemm_tc<0><<<grid, GEMM_THREADS, GEMM_SMEM>>>(
            xf, wt, bq, bk, bv, q, k, v);
    }

    // 4) attention
    attention_kernel<<<BATCH * NHEAD, 256, ATT_SMEM>>>(q, k, v, att, attn_out);

    // 5) output projection (+ transpose back to [B, E, H, W])
    {
        dim3 grid(EMB / BN, MROWS / BM);
        gemm_tc<1><<<grid, GEMM_THREADS, GEMM_SMEM>>>(
            att, wt + 3 * WSTRIDE, bo, nullptr, nullptr, out, nullptr, nullptr);
    }
}

// round 11
// speedup vs baseline: 4.2863x; 1.0400x over previous
#include <cuda_runtime.h>
#include <cuda_fp16.h>
#include <cstdint>

// Problem constants
#define BATCH 256
#define EMB   1024
#define SEQ   100
#define NHEAD 16
#define HDIM  64
#define MROWS (BATCH * SEQ)   // 25600

// GEMM tiling
#define BM 128
#define BN 128
#define BK 64
#define STAGES 3
#define GEMM_THREADS 256
#define ROW_B     144                    // 128B data + 16B pad (conflict-free ldmatrix)
#define MAT_BYTES (128 * ROW_B)          // 18432
#define STAGE_BYTES (2 * MAT_BYTES)      // 36864
#define GEMM_SMEM (STAGES * STAGE_BYTES) // 110592

// ---------------- scratch (__device__ globals; no allocation) ----------------
__device__ __half g_xf[(size_t)MROWS * EMB];          // [b*S+s][e]
__device__ __half g_wt[(size_t)4 * EMB * EMB];        // [mat][n][k] = W[k][n]
__device__ __half g_q[(size_t)MROWS * EMB];           // [b][h][d][s]
__device__ __half g_k[(size_t)MROWS * EMB];           // [b][h][d][s]
__device__ __half g_v[(size_t)MROWS * EMB];           // [b][h][d][s]
__device__ __half g_att[(size_t)MROWS * EMB];         // [b*S+s][e]

// ---------------- helpers ----------------
__device__ __forceinline__ uint32_t smem_u32(const void* p) {
    return (uint32_t)__cvta_generic_to_shared(p);
}
__device__ __forceinline__ void cp16(uint32_t dst, const void* src) {
    asm volatile("cp.async.cg.shared.global [%0], [%1], 16;" :: "r"(dst), "l"(src));
}
__device__ __forceinline__ void ldmx4(uint32_t addr, uint32_t* r) {
    asm volatile("ldmatrix.sync.aligned.m8n8.x4.shared.b16 {%0,%1,%2,%3}, [%4];"
                 : "=r"(r[0]), "=r"(r[1]), "=r"(r[2]), "=r"(r[3]) : "r"(addr));
}
__device__ __forceinline__ void mma_fp16(float* d, const uint32_t* a, const uint32_t* b) {
    asm volatile(
        "mma.sync.aligned.m16n8k16.row.col.f32.f16.f16.f32 "
        "{%0,%1,%2,%3}, {%4,%5,%6,%7}, {%8,%9}, {%0,%1,%2,%3};"
        : "+f"(d[0]), "+f"(d[1]), "+f"(d[2]), "+f"(d[3])
        : "r"(a[0]), "r"(a[1]), "r"(a[2]), "r"(a[3]), "r"(b[0]), "r"(b[1]));
}

// ---------------- kernel 1: x [B,E,S] -> xflat fp16 [B*S, E], + pos ----------
__global__ void transpose_pos_kernel(const float* __restrict__ x,
                                     const float* __restrict__ pos,
                                     __half* __restrict__ xf) {
    __shared__ float tile[32][33];
    int b  = blockIdx.z;
    int e0 = blockIdx.y * 32;
    int s0 = blockIdx.x * 32;
    int tx = threadIdx.x, ty = threadIdx.y;

    int s = s0 + tx;
    if (s < SEQ)
        tile[ty][tx] = x[(size_t)b * EMB * SEQ + (size_t)(e0 + ty) * SEQ + s];
    __syncthreads();

    int s2 = s0 + ty, e2 = e0 + tx;
    if (s2 < SEQ) {
        float v = tile[tx][ty] + pos[(size_t)s2 * EMB + e2];
        xf[((size_t)b * SEQ + s2) * EMB + e2] = __float2half(v);
    }
}

// ---------------- kernel 2: weight transpose: W[k][n] -> WT[n][k] fp16 ------
__global__ void wconvert_kernel(const float* __restrict__ W,
                                __half* __restrict__ t_out) {
    __shared__ float t[32][33];
    int n0 = blockIdx.x * 32, k0 = blockIdx.y * 32;
    int tx = threadIdx.x, ty = threadIdx.y;
    t[ty][tx] = W[(size_t)(k0 + ty) * EMB + n0 + tx];
    __syncthreads();
    t_out[(size_t)(n0 + ty) * EMB + k0 + tx] = __float2half(t[tx][ty]);
}

// ---------------- kernel 3: fp16 HMMA GEMM (BK=64) ----------------
// C = A[M,K] @ B^T[N,K] + bias
// MODE 0: fused QKV, N = 3072; per-CTA mat select; scatter fp16 to [b,h,d,s].
// MODE 1: O projection, N = 1024; scatter fp32 to out [b,n,s].
__device__ __forceinline__ void load_stage(
    char* sb, const __half* __restrict__ A, const __half* __restrict__ B,
    int bm, int bn, int k0, int tid) {
    uint32_t sbase = smem_u32(sb);
#pragma unroll
    for (int i = 0; i < 4; i++) {
        int idx = tid + i * GEMM_THREADS;     // 0..1023
        int row = idx >> 3, c16 = idx & 7;    // 8 x 16B chunks per 128B row
        uint32_t dst = sbase + (uint32_t)(row * ROW_B + c16 * 16);
        cp16(dst,             A + (size_t)(bm + row) * EMB + k0 + c16 * 8);
        cp16(dst + MAT_BYTES, B + (size_t)(bn + row) * EMB + k0 + c16 * 8);
    }
    asm volatile("cp.async.commit_group;" ::: "memory");
}

template <int MODE>
__global__ __launch_bounds__(GEMM_THREADS, 2)
void gemm_tc(const __half* __restrict__ A, const __half* __restrict__ B,
             const float* __restrict__ bias0, const float* __restrict__ bias1,
             const float* __restrict__ bias2,
             void* __restrict__ C0v, void* __restrict__ C1v, void* __restrict__ C2v) {
    extern __shared__ char dsm[];
    const int tid = threadIdx.x;
    const int lane = tid & 31;
    const int wid = tid >> 5;
    const int warpM = wid & 3;        // 4 warps along M (32 rows each)
    const int warpN = wid >> 2;       // 2 warps along N (64 cols each)
    const int bm = blockIdx.y * BM;
    const int bn = blockIdx.x * BN;

    const int mat = bn >> 10;
    void* Cv = (MODE == 0) ? (mat == 0 ? C0v : (mat == 1 ? C1v : C2v)) : C0v;
    const float* bias = (MODE == 0) ? (mat == 0 ? bias0 : (mat == 1 ? bias1 : bias2)) : bias0;

    float acc[2][8][4];
#pragma unroll
    for (int i = 0; i < 2; i++)
#pragma unroll
        for (int j = 0; j < 8; j++)
#pragma unroll
            for (int r = 0; r < 4; r++) acc[i][j][r] = 0.f;

    load_stage(dsm + 0 * STAGE_BYTES, A, B, bm, bn, 0 * BK, tid);
    load_stage(dsm + 1 * STAGE_BYTES, A, B, bm, bn, 1 * BK, tid);

    const int NK = EMB / BK;          // 16

    const uint32_t a_row = (uint32_t)(warpM * 32 + (lane & 15));
    const uint32_t a_koff = (uint32_t)((lane >> 4) * 16);
    const uint32_t b_row = (uint32_t)(warpN * 64 + (lane & 7) + ((lane >> 4) & 1) * 8);
    const uint32_t b_koff = (uint32_t)(((lane >> 3) & 1) * 16);

    for (int kc = 0; kc < NK; kc++) {
        asm volatile("cp.async.wait_group %0;" :: "n"(STAGES - 2) : "memory");
        __syncthreads();

        if (kc + STAGES - 1 < NK) {
            load_stage(dsm + ((kc + STAGES - 1) % STAGES) * STAGE_BYTES,
                       A, B, bm, bn, (kc + STAGES - 1) * BK, tid);
        } else {
            asm volatile("cp.async.commit_group;" ::: "memory");
        }

        uint32_t sb = smem_u32(dsm) + (uint32_t)((kc % STAGES) * STAGE_BYTES);
        uint32_t sA = sb, sB = sb + MAT_BYTES;

#pragma unroll
        for (int ks = 0; ks < 4; ks++) {          // 4 K=16 slices per BK=64
            const uint32_t kb = (uint32_t)(ks * 32);  // bytes
            uint32_t af[2][4], bf[4][4];
#pragma unroll
            for (int mi = 0; mi < 2; mi++)
                ldmx4(sA + (a_row + mi * 16) * ROW_B + kb + a_koff, af[mi]);
#pragma unroll
            for (int nb = 0; nb < 4; nb++)
                ldmx4(sB + (b_row + nb * 16) * ROW_B + kb + b_koff, bf[nb]);
#pragma unroll
            for (int mi = 0; mi < 2; mi++)
#pragma unroll
                for (int ni = 0; ni < 8; ni++)
                    mma_fp16(acc[mi][ni], af[mi], &bf[ni >> 1][(ni & 1) * 2]);
        }
    }

    // epilogue
    const int r0 = lane >> 2;
    const int c0 = (lane & 3) * 2;
#pragma unroll
    for (int mi = 0; mi < 2; mi++) {
        int mbase = bm + warpM * 32 + mi * 16;
#pragma unroll
        for (int ni = 0; ni < 8; ni++) {
            int n = bn + warpN * 64 + ni * 8 + c0;
            int nn = n & 1023;
            float bia0 = bias[nn], bia1 = bias[nn + 1];
#pragma unroll
            for (int half = 0; half < 2; half++) {
                int m = mbase + r0 + half * 8;
                int bb = m / SEQ, s = m - bb * SEQ;
                float v0 = acc[mi][ni][half * 2 + 0] + bia0;
                float v1 = acc[mi][ni][half * 2 + 1] + bia1;
                if (MODE == 0) {
                    __half* C = (__half*)Cv;
                    size_t base0 = (((size_t)bb * NHEAD + (nn >> 6)) * HDIM + (nn & 63));
                    C[base0 * SEQ + s] = __float2half(v0);
                    size_t base1 = (((size_t)bb * NHEAD + ((nn + 1) >> 6)) * HDIM + ((nn + 1) & 63));
                    C[base1 * SEQ + s] = __float2half(v1);
                } else {
                    float* C = (float*)Cv;
                    C[((size_t)bb * EMB + n) * SEQ + s] = v0;
                    C[((size_t)bb * EMB + n + 1) * SEQ + s] = v1;
                }
            }
        }
    }
}

// ---------------- kernel 4: register-tiled fused attention per (b,h) -------
// q,k,v fp16 in [b,h,d,s]; writes attn probs (optional) and att fp16 [b*S+s][e]
#define SP 112                 // padded S (16 x 7)
#define VT_STRIDE 101
#define ATT_SMEM ((64 * SP + 64 * SP + 64 * VT_STRIDE + SP * SP) * 4)  // 133376
__global__ __launch_bounds__(256)
void attention_kernel(const __half* __restrict__ Q, const __half* __restrict__ Kg,
                      const __half* __restrict__ V,
                      __half* __restrict__ att,
                      float* __restrict__ attn_out) {
    extern __shared__ float sm[];
    float* qT = sm;                         // [64][112]  ([d][s])
    float* kT = qT + 64 * SP;               // [64][112]
    float* vT = kT + 64 * SP;               // [64][101]
    float* Ps = vT + 64 * VT_STRIDE;        // [112][112]

    int bh = blockIdx.x;
    int b = bh >> 4, h = bh & 15;
    int tid = threadIdx.x;

    const __half* Qg = Q + (size_t)bh * (SEQ * HDIM);
    const __half* Kp = Kg + (size_t)bh * (SEQ * HDIM);
    const __half* Vg = V + (size_t)bh * (SEQ * HDIM);

    for (int idx = tid; idx < 64 * SP; idx += 256) {
        int d = idx / SP, s = idx - d * SP;
        float qv = 0.f, kv = 0.f;
        if (s < SEQ) {
            qv = __half2float(Qg[d * SEQ + s]);
            kv = __half2float(Kp[d * SEQ + s]);
        }
        qT[idx] = qv;
        kT[idx] = kv;
    }
    for (int idx = tid; idx < 64 * VT_STRIDE; idx += 256) {
        int d = idx / VT_STRIDE, s = idx - d * VT_STRIDE;
        vT[idx] = (s < SEQ) ? __half2float(Vg[d * SEQ + s]) : 0.f;
    }
    __syncthreads();

    const int ti = tid >> 4, tj = tid & 15;
    const int i0 = ti * 7, j0 = tj * 7;

    // ---- scores = Q K^T / 8 (7x7 register tile per thread) ----
    {
        float acc[7][7];
#pragma unroll
        for (int a = 0; a < 7; a++)
#pragma unroll
            for (int bq = 0; bq < 7; bq++) acc[a][bq] = 0.f;

        for (int d = 0; d < HDIM; d++) {
            float qv[7], kv[7];
#pragma unroll
            for (int a = 0; a < 7; a++) qv[a] = qT[d * SP + i0 + a];
#pragma unroll
            for (int bq = 0; bq < 7; bq++) kv[bq] = kT[d * SP + j0 + bq];
#pragma unroll
            for (int a = 0; a < 7; a++)
#pragma unroll
                for (int bq = 0; bq < 7; bq++)
                    acc[a][bq] = fmaf(qv[a], kv[bq], acc[a][bq]);
        }
#pragma unroll
        for (int a = 0; a < 7; a++) {
            int i = i0 + a;
#pragma unroll
            for (int bq = 0; bq < 7; bq++) {
                int j = j0 + bq;
                Ps[i * SP + j] = (j < SEQ) ? acc[a][bq] * 0.125f : -1e30f;
            }
        }
    }
    __syncthreads();

    // ---- row softmax (one warp per row) ----
    {
        int warp = tid >> 5, lane = tid & 31;
        for (int i = warp; i < SEQ; i += 8) {
            float* row = Ps + i * SP;
            float mx = -1e30f;
            for (int j = lane; j < SP; j += 32) mx = fmaxf(mx, row[j]);
#pragma unroll
            for (int o = 16; o > 0; o >>= 1) mx = fmaxf(mx, __shfl_xor_sync(0xffffffffu, mx, o));
            float sum = 0.f;
            for (int j = lane; j < SP; j += 32) {
                float e = __expf(row[j] - mx);
                row[j] = e;
                sum += e;
            }
#pragma unroll
            for (int o = 16; o > 0; o >>= 1) sum += __shfl_xor_sync(0xffffffffu, sum, o);
            float inv = 1.0f / sum;
            for (int j = lane; j < SP; j += 32) row[j] *= inv;
        }
    }
    __syncthreads();

    if (attn_out != nullptr) {
        float* dst = attn_out + (size_t)bh * (SEQ * SEQ);
        for (int p = tid; p < SEQ * SEQ; p += 256) {
            int i = p / SEQ, j = p - (p / SEQ) * SEQ;
            dst[p] = Ps[i * SP + j];
        }
    }

    // ---- attended = P @ V (7x4 register tile; dd = tj + 16c, conflict-free) --
    {
        float pacc[7][4];
#pragma unroll
        for (int a = 0; a < 7; a++)
#pragma unroll
            for (int c = 0; c < 4; c++) pacc[a][c] = 0.f;

        for (int j = 0; j < SEQ; j++) {
            float pv[7], vv[4];
#pragma unroll
            for (int a = 0; a < 7; a++) pv[a] = Ps[(i0 + a) * SP + j];
#pragma unroll
            for (int c = 0; c < 4; c++) vv[c] = vT[(tj + c * 16) * VT_STRIDE + j];
#pragma unroll
            for (int a = 0; a < 7; a++)
#pragma unroll
                for (int c = 0; c < 4; c++)
                    pacc[a][c] = fmaf(pv[a], vv[c], pacc[a][c]);
        }
#pragma unroll
        for (int a = 0; a < 7; a++) {
            int i = i0 + a;
            if (i >= SEQ) continue;
#pragma unroll
            for (int c = 0; c < 4; c++) {
                int dd = tj + c * 16;
                size_t dst = ((size_t)b * SEQ + i) * EMB + h * HDIM + dd;
                att[dst] = __float2half(pacc[a][c]);
            }
        }
    }
}

// ---------------- launch ----------------
extern "C" void kernel_launch(void* const* d_in, const int* in_sizes, int n_in,
                              void* d_out, int out_size) {
    const float* x   = (const float*)d_in[0];
    const float* Wq  = (const float*)d_in[1];
    const float* bq  = (const float*)d_in[2];
    const float* Wk  = (const float*)d_in[3];
    const float* bk  = (const float*)d_in[4];
    const float* Wv  = (const float*)d_in[5];
    const float* bv  = (const float*)d_in[6];
    const float* Wo  = (const float*)d_in[7];
    const float* bo  = (const float*)d_in[8];
    const float* pos = (const float*)d_in[9];

    float* out = (float*)d_out;
    const size_t out_elems = (size_t)BATCH * EMB * SEQ;
    float* attn_out = ((size_t)out_size > out_elems) ? out + out_elems : nullptr;

    __half *xf, *wt, *att, *q, *k, *v;
    cudaGetSymbolAddress((void**)&xf,  g_xf);
    cudaGetSymbolAddress((void**)&wt,  g_wt);
    cudaGetSymbolAddress((void**)&q,   g_q);
    cudaGetSymbolAddress((void**)&k,   g_k);
    cudaGetSymbolAddress((void**)&v,   g_v);
    cudaGetSymbolAddress((void**)&att, g_att);

    cudaFuncSetAttribute(gemm_tc<0>, cudaFuncAttributeMaxDynamicSharedMemorySize, GEMM_SMEM);
    cudaFuncSetAttribute(gemm_tc<1>, cudaFuncAttributeMaxDynamicSharedMemorySize, GEMM_SMEM);
    cudaFuncSetAttribute(attention_kernel, cudaFuncAttributeMaxDynamicSharedMemorySize, ATT_SMEM);

    const size_t WSTRIDE = (size_t)EMB * EMB;

    // 1) weight transpose to K-major fp16
    {
        dim3 grid(EMB / 32, EMB / 32);
        dim3 blk(32, 32);
        wconvert_kernel<<<grid, blk>>>(Wq, wt + 0 * WSTRIDE);
        wconvert_kernel<<<grid, blk>>>(Wk, wt + 1 * WSTRIDE);
        wconvert_kernel<<<grid, blk>>>(Wv, wt + 2 * WSTRIDE);
        wconvert_kernel<<<grid, blk>>>(Wo, wt + 3 * WSTRIDE);
    }

    // 2) transpose + pos -> fp16
    {
        dim3 grid((SEQ + 31) / 32, EMB / 32, BATCH);
        dim3 blk(32, 32);
        transpose_pos_kernel<<<grid, blk>>>(x, pos, xf);
    }

    // 3) fused Q/K/V projection (one GEMM over N=3072)
    {
        dim3 grid(3 * EMB / BN, MROWS / BM);   // (24, 200)
        gemm_tc<0><<<grid, GEMM_THREADS, GEMM_SMEM>>>(
            xf, wt, bq, bk, bv, q, k, v);
    }

    // 4) attention
    attention_kernel<<<BATCH * NHEAD, 256, ATT_SMEM>>>(q, k, v, att, attn_out);

    // 5) output projection (+ transpose back to [B, E, H, W])
    {
        dim3 grid(EMB / BN, MROWS / BM);
        gemm_tc<1><<<grid, GEMM_THREADS, GEMM_SMEM>>>(
            att, wt + 3 * WSTRIDE, bo, nullptr, nullptr, out, nullptr, nullptr);
    }
}

// round 13
// speedup vs baseline: 5.5998x; 1.3065x over previous
#include <cuda_runtime.h>
#include <cuda_fp16.h>
#include <cstdint>

// Problem constants
#define BATCH 256
#define EMB   1024
#define SEQ   100
#define NHEAD 16
#define HDIM  64
#define MROWS (BATCH * SEQ)   // 25600

// GEMM tiling
#define BM 128
#define BN 128
#define BK 64
#define STAGES 3
#define GEMM_THREADS 256
#define ROW_B     144                    // 128B data + 16B pad (conflict-free ldmatrix)
#define MAT_BYTES (128 * ROW_B)          // 18432
#define STAGE_BYTES (2 * MAT_BYTES)      // 36864
#define GEMM_SMEM (STAGES * STAGE_BYTES) // 110592

// ---------------- scratch (__device__ globals; no allocation) ----------------
__device__ __half g_xf[(size_t)MROWS * EMB];          // [b*S+s][e]
__device__ __half g_wt[(size_t)4 * EMB * EMB];        // [mat][n][k] = W[k][n]
__device__ __half g_q[(size_t)MROWS * EMB];           // [b][h][s][d]
__device__ __half g_k[(size_t)MROWS * EMB];           // [b][h][s][d]
__device__ __half g_v[(size_t)MROWS * EMB];           // [b][h][s][d]
__device__ __half g_att[(size_t)MROWS * EMB];         // [b*S+s][e]

// ---------------- helpers ----------------
__device__ __forceinline__ uint32_t smem_u32(const void* p) {
    return (uint32_t)__cvta_generic_to_shared(p);
}
__device__ __forceinline__ void cp16(uint32_t dst, const void* src) {
    asm volatile("cp.async.cg.shared.global [%0], [%1], 16;" :: "r"(dst), "l"(src));
}
__device__ __forceinline__ void ldmx4(uint32_t addr, uint32_t* r) {
    asm volatile("ldmatrix.sync.aligned.m8n8.x4.shared.b16 {%0,%1,%2,%3}, [%4];"
                 : "=r"(r[0]), "=r"(r[1]), "=r"(r[2]), "=r"(r[3]) : "r"(addr));
}
__device__ __forceinline__ void mma_fp16(float* d, const uint32_t* a, const uint32_t* b) {
    asm volatile(
        "mma.sync.aligned.m16n8k16.row.col.f32.f16.f16.f32 "
        "{%0,%1,%2,%3}, {%4,%5,%6,%7}, {%8,%9}, {%0,%1,%2,%3};"
        : "+f"(d[0]), "+f"(d[1]), "+f"(d[2]), "+f"(d[3])
        : "r"(a[0]), "r"(a[1]), "r"(a[2]), "r"(a[3]), "r"(b[0]), "r"(b[1]));
}

// ---------------- kernel 1: x [B,E,S] -> xflat fp16 [B*S, E], + pos ----------
__global__ void transpose_pos_kernel(const float* __restrict__ x,
                                     const float* __restrict__ pos,
                                     __half* __restrict__ xf) {
    __shared__ float tile[32][33];
    int b  = blockIdx.z;
    int e0 = blockIdx.y * 32;
    int s0 = blockIdx.x * 32;
    int tx = threadIdx.x, ty = threadIdx.y;

    int s = s0 + tx;
    if (s < SEQ)
        tile[ty][tx] = x[(size_t)b * EMB * SEQ + (size_t)(e0 + ty) * SEQ + s];
    __syncthreads();

    int s2 = s0 + ty, e2 = e0 + tx;
    if (s2 < SEQ) {
        float v = tile[tx][ty] + pos[(size_t)s2 * EMB + e2];
        xf[((size_t)b * SEQ + s2) * EMB + e2] = __float2half(v);
    }
}

// ---------------- kernel 2: weight transpose: W[k][n] -> WT[n][k] fp16 ------
__global__ void wconvert_kernel(const float* __restrict__ W,
                                __half* __restrict__ t_out) {
    __shared__ float t[32][33];
    int n0 = blockIdx.x * 32, k0 = blockIdx.y * 32;
    int tx = threadIdx.x, ty = threadIdx.y;
    t[ty][tx] = W[(size_t)(k0 + ty) * EMB + n0 + tx];
    __syncthreads();
    t_out[(size_t)(n0 + ty) * EMB + k0 + tx] = __float2half(t[tx][ty]);
}

// ---------------- kernel 3: fp16 HMMA GEMM (BK=64) ----------------
// C = A[M,K] @ B^T[N,K] + bias
// MODE 0: fused QKV, N = 3072; per-CTA mat select; half2 store to [b,h,s,d].
// MODE 1: O projection, N = 1024; smem-staged coalesced store to out [b,n,s].
__device__ __forceinline__ void load_stage(
    char* sb, const __half* __restrict__ A, const __half* __restrict__ B,
    int bm, int bn, int k0, int tid) {
    uint32_t sbase = smem_u32(sb);
#pragma unroll
    for (int i = 0; i < 4; i++) {
        int idx = tid + i * GEMM_THREADS;     // 0..1023
        int row = idx >> 3, c16 = idx & 7;    // 8 x 16B chunks per 128B row
        uint32_t dst = sbase + (uint32_t)(row * ROW_B + c16 * 16);
        cp16(dst,             A + (size_t)(bm + row) * EMB + k0 + c16 * 8);
        cp16(dst + MAT_BYTES, B + (size_t)(bn + row) * EMB + k0 + c16 * 8);
    }
    asm volatile("cp.async.commit_group;" ::: "memory");
}

#define CS_STRIDE 132

template <int MODE>
__global__ __launch_bounds__(GEMM_THREADS, 2)
void gemm_tc(const __half* __restrict__ A, const __half* __restrict__ B,
             const float* __restrict__ bias0, const float* __restrict__ bias1,
             const float* __restrict__ bias2,
             void* __restrict__ C0v, void* __restrict__ C1v, void* __restrict__ C2v) {
    extern __shared__ char dsm[];
    const int tid = threadIdx.x;
    const int lane = tid & 31;
    const int wid = tid >> 5;
    const int warpM = wid & 3;        // 4 warps along M (32 rows each)
    const int warpN = wid >> 2;       // 2 warps along N (64 cols each)
    const int bm = blockIdx.y * BM;
    const int bn = blockIdx.x * BN;

    const int mat = bn >> 10;
    void* Cv = (MODE == 0) ? (mat == 0 ? C0v : (mat == 1 ? C1v : C2v)) : C0v;
    const float* bias = (MODE == 0) ? (mat == 0 ? bias0 : (mat == 1 ? bias1 : bias2)) : bias0;

    float acc[2][8][4];
#pragma unroll
    for (int i = 0; i < 2; i++)
#pragma unroll
        for (int j = 0; j < 8; j++)
#pragma unroll
            for (int r = 0; r < 4; r++) acc[i][j][r] = 0.f;

    load_stage(dsm + 0 * STAGE_BYTES, A, B, bm, bn, 0 * BK, tid);
    load_stage(dsm + 1 * STAGE_BYTES, A, B, bm, bn, 1 * BK, tid);

    const int NK = EMB / BK;          // 16

    const uint32_t a_row = (uint32_t)(warpM * 32 + (lane & 15));
    const uint32_t a_koff = (uint32_t)((lane >> 4) * 16);
    const uint32_t b_row = (uint32_t)(warpN * 64 + (lane & 7) + ((lane >> 4) & 1) * 8);
    const uint32_t b_koff = (uint32_t)(((lane >> 3) & 1) * 16);

    for (int kc = 0; kc < NK; kc++) {
        asm volatile("cp.async.wait_group %0;" :: "n"(STAGES - 2) : "memory");
        __syncthreads();

        if (kc + STAGES - 1 < NK) {
            load_stage(dsm + ((kc + STAGES - 1) % STAGES) * STAGE_BYTES,
                       A, B, bm, bn, (kc + STAGES - 1) * BK, tid);
        } else {
            asm volatile("cp.async.commit_group;" ::: "memory");
        }

        uint32_t sb = smem_u32(dsm) + (uint32_t)((kc % STAGES) * STAGE_BYTES);
        uint32_t sA = sb, sB = sb + MAT_BYTES;

#pragma unroll
        for (int ks = 0; ks < 4; ks++) {          // 4 K=16 slices per BK=64
            const uint32_t kb = (uint32_t)(ks * 32);  // bytes
            uint32_t af[2][4], bf[4][4];
#pragma unroll
            for (int mi = 0; mi < 2; mi++)
                ldmx4(sA + (a_row + mi * 16) * ROW_B + kb + a_koff, af[mi]);
#pragma unroll
            for (int nb = 0; nb < 4; nb++)
                ldmx4(sB + (b_row + nb * 16) * ROW_B + kb + b_koff, bf[nb]);
#pragma unroll
            for (int mi = 0; mi < 2; mi++)
#pragma unroll
                for (int ni = 0; ni < 8; ni++)
                    mma_fp16(acc[mi][ni], af[mi], &bf[ni >> 1][(ni & 1) * 2]);
        }
    }

    const int r0 = lane >> 2;
    const int c0 = (lane & 3) * 2;

    if (MODE == 0) {
        // half2 store to [b, h, s, d] — d pairs contiguous
        __half* C = (__half*)Cv;
#pragma unroll
        for (int mi = 0; mi < 2; mi++) {
            int mbase = bm + warpM * 32 + mi * 16;
#pragma unroll
            for (int ni = 0; ni < 8; ni++) {
                int n = bn + warpN * 64 + ni * 8 + c0;
                int nn = n & 1023;
                int hh = nn >> 6, d = nn & 63;
                float bia0 = bias[nn], bia1 = bias[nn + 1];
#pragma unroll
                for (int half = 0; half < 2; half++) {
                    int m = mbase + r0 + half * 8;
                    int bb = m / SEQ, s = m - bb * SEQ;
                    float v0 = acc[mi][ni][half * 2 + 0] + bia0;
                    float v1 = acc[mi][ni][half * 2 + 1] + bia1;
                    size_t base = (((size_t)bb * NHEAD + hh) * SEQ + s) * HDIM + d;
                    *reinterpret_cast<__half2*>(&C[base]) = __floats2half2_rn(v0, v1);
                }
            }
        }
    } else {
        // stage into smem [n][m], then coalesced write to out [b, n, s]
        asm volatile("cp.async.wait_group 0;" ::: "memory");
        __syncthreads();
        float* Cs = (float*)dsm;
#pragma unroll
        for (int mi = 0; mi < 2; mi++) {
            int mloc0 = warpM * 32 + mi * 16;
#pragma unroll
            for (int ni = 0; ni < 8; ni++) {
                int nloc = warpN * 64 + ni * 8 + c0;
                float bia0 = bias[bn + nloc], bia1 = bias[bn + nloc + 1];
#pragma unroll
                for (int half = 0; half < 2; half++) {
                    int mloc = mloc0 + r0 + half * 8;
                    Cs[nloc * CS_STRIDE + mloc]       = acc[mi][ni][half * 2 + 0] + bia0;
                    Cs[(nloc + 1) * CS_STRIDE + mloc] = acc[mi][ni][half * 2 + 1] + bia1;
                }
            }
        }
        __syncthreads();
        float* C = (float*)Cv;
#pragma unroll
        for (int nr = 0; nr < 16; nr++) {
            int nloc = wid * 16 + nr;
            int n = bn + nloc;
#pragma unroll
            for (int t = 0; t < 4; t++) {
                int mloc = lane + 32 * t;
                int m = bm + mloc;
                int bb = m / SEQ, s = m - bb * SEQ;
                C[((size_t)bb * EMB + n) * SEQ + s] = Cs[nloc * CS_STRIDE + mloc];
            }
        }
    }
}

// ---------------- kernel 4: HMMA attention per (b,h) ----------------
// q,k,v fp16 [b,h,s,d]; writes attn probs (optional) and att fp16 [b*S+s][e]
// M padded to 128 (8 warps x m16); score/KV cols padded to 112.
#define MPAD 128
#define SPAD 112
#define QF_STR 72        // halves (144B rows)
#define VF_STR 120       // halves (240B rows)
#define PF_STR 120
#define PS_STR 116       // floats
#define OFF_QF 0
#define OFF_KF 18432                              // Qf: 128*72*2
#define OFF_VF (OFF_KF + 16128)                   // Kf: 112*72*2 -> 34560
#define OFF_PS (OFF_VF + 15360)                   // Vf: 64*120*2 -> 49920
#define ATT_SMEM (OFF_PS + MPAD * PS_STR * 4)     // 49920 + 59392 = 109312
__global__ __launch_bounds__(256, 2)
void attention_kernel(const __half* __restrict__ Q, const __half* __restrict__ Kg,
                      const __half* __restrict__ V,
                      __half* __restrict__ att,
                      float* __restrict__ attn_out) {
    extern __shared__ char asmem[];
    __half* Qf = (__half*)(asmem + OFF_QF);      // [128][72]  rows >= SEQ zero
    __half* Kf = (__half*)(asmem + OFF_KF);      // [112][72]  rows >= SEQ zero
    __half* Vf = (__half*)(asmem + OFF_VF);      // [64][120]  (V^T: [d][s]) cols >= SEQ zero
    __half* Pf = (__half*)(asmem + OFF_QF);      // [128][120] overlays Qf+Kf (30720 <= 34560)
    float*  Ps = (float*)(asmem + OFF_PS);       // [128][116]

    int bh = blockIdx.x;
    int b = bh >> 4, h = bh & 15;
    int tid = threadIdx.x;
    int lane = tid & 31, wid = tid >> 5;

    const __half* Qg = Q + (size_t)bh * (SEQ * HDIM);   // [s][d]
    const __half* Kp = Kg + (size_t)bh * (SEQ * HDIM);
    const __half* Vg = V + (size_t)bh * (SEQ * HDIM);

    // fill Qf (128 rows, zero-padded), Kf (112 rows, zero-padded)
    for (int idx = tid; idx < MPAD * HDIM; idx += 256) {
        int s = idx >> 6, d = idx & 63;
        __half qv = __float2half(0.f);
        if (s < SEQ) qv = Qg[s * HDIM + d];
        Qf[s * QF_STR + d] = qv;
        if (s < SPAD) {
            __half kv = __float2half(0.f);
            if (s < SEQ) kv = Kp[s * HDIM + d];
            Kf[s * QF_STR + d] = kv;
        }
    }
    // Vf transposed [d][s], cols >= SEQ zeroed
    for (int idx = tid; idx < HDIM * SPAD; idx += 256) {
        int d = idx / SPAD, s = idx - d * SPAD;
        Vf[d * VF_STR + s] = (s < SEQ) ? Vg[s * HDIM + d] : __float2half(0.f);
    }
    __syncthreads();

    const uint32_t a_row = (uint32_t)(lane & 15);
    const uint32_t a_koff = (uint32_t)((lane >> 4) * 16);
    const uint32_t b_row = (uint32_t)((lane & 7) + ((lane >> 4) & 1) * 8);
    const uint32_t b_koff = (uint32_t)(((lane >> 3) & 1) * 16);
    const int r0 = lane >> 2, c0 = (lane & 3) * 2;

    // ---- scores = Q K^T / 8 : warp w -> m16 rows [w*16, w*16+16) of 128 ----
    {
        float acc[14][4];
#pragma unroll
        for (int i = 0; i < 14; i++)
#pragma unroll
            for (int r = 0; r < 4; r++) acc[i][r] = 0.f;

        uint32_t qb = smem_u32(Qf) + (wid * 16 + a_row) * (QF_STR * 2) + a_koff;
        uint32_t kb = smem_u32(Kf) + b_row * (QF_STR * 2) + b_koff;
#pragma unroll
        for (int ks = 0; ks < 4; ks++) {
            uint32_t ko = (uint32_t)(ks * 32);
            uint32_t af[4];
            ldmx4(qb + ko, af);
#pragma unroll
            for (int nt = 0; nt < 7; nt++) {      // B rows nt*16 + b_row <= 111
                uint32_t bf[4];
                ldmx4(kb + nt * 16 * (QF_STR * 2) + ko, bf);
                mma_fp16(acc[nt * 2 + 0], af, &bf[0]);
                mma_fp16(acc[nt * 2 + 1], af, &bf[2]);
            }
        }
#pragma unroll
        for (int ni = 0; ni < 14; ni++) {
            int n = ni * 8 + c0;
            float s0 = (n < SEQ) ? acc[ni][0] * 0.125f : -1e30f;
            float s1 = (n + 1 < SEQ) ? acc[ni][1] * 0.125f : -1e30f;
            float s2 = (n < SEQ) ? acc[ni][2] * 0.125f : -1e30f;
            float s3 = (n + 1 < SEQ) ? acc[ni][3] * 0.125f : -1e30f;
            int i = wid * 16 + r0;                // i in [0,128), Ps has 128 rows
            Ps[i * PS_STR + n] = s0;
            Ps[i * PS_STR + n + 1] = s1;
            Ps[(i + 8) * PS_STR + n] = s2;
            Ps[(i + 8) * PS_STR + n + 1] = s3;
        }
    }
    __syncthreads();

    // ---- row softmax (one warp per row, rows < SEQ) ----
    for (int i = wid; i < SEQ; i += 8) {
        float* row = Ps + i * PS_STR;
        float mx = -1e30f;
        for (int j = lane; j < SPAD; j += 32) mx = fmaxf(mx, row[j]);
#pragma unroll
        for (int o = 16; o > 0; o >>= 1) mx = fmaxf(mx, __shfl_xor_sync(0xffffffffu, mx, o));
        float sum = 0.f;
        for (int j = lane; j < SPAD; j += 32) {
            float e = __expf(row[j] - mx);
            row[j] = e;
            sum += e;
        }
#pragma unroll
        for (int o = 16; o > 0; o >>= 1) sum += __shfl_xor_sync(0xffffffffu, sum, o);
        float inv = 1.0f / sum;
        for (int j = lane; j < SPAD; j += 32) row[j] *= inv;
    }
    __syncthreads();

    // ---- attn probs out + P -> fp16 (overlays Qf/Kf) ----
    if (attn_out != nullptr) {
        float* dst = attn_out + (size_t)bh * (SEQ * SEQ);
        for (int p = tid; p < SEQ * SEQ; p += 256) {
            int i = p / SEQ, j = p - (p / SEQ) * SEQ;
            dst[p] = Ps[i * PS_STR + j];
        }
    }
    for (int p = tid; p < MPAD * SPAD; p += 256) {
        int i = p / SPAD, j = p - (p / SPAD) * SPAD;
        float v = (i < SEQ) ? Ps[i * PS_STR + j] : 0.f;
        Pf[i * PF_STR + j] = __float2half(v);
    }
    __syncthreads();

    // ---- attended = P @ V : A = Pf [128 x K=112], B = Vf [d][j] ----
    {
        float acc[8][4];
#pragma unroll
        for (int i = 0; i < 8; i++)
#pragma unroll
            for (int r = 0; r < 4; r++) acc[i][r] = 0.f;

        uint32_t pb = smem_u32(Pf) + (wid * 16 + a_row) * (PF_STR * 2) + a_koff;
        uint32_t vb = smem_u32(Vf) + b_row * (VF_STR * 2) + b_koff;
#pragma unroll
        for (int ks = 0; ks < 7; ks++) {          // K = 112
            uint32_t ko = (uint32_t)(ks * 32);
            uint32_t af[4];
            ldmx4(pb + ko, af);
#pragma unroll
            for (int nt = 0; nt < 4; nt++) {      // d rows nt*16 + b_row <= 63
                uint32_t bf[4];
                ldmx4(vb + nt * 16 * (VF_STR * 2) + ko, bf);
                mma_fp16(acc[nt * 2 + 0], af, &bf[0]);
                mma_fp16(acc[nt * 2 + 1], af, &bf[2]);
            }
        }
#pragma unroll
        for (int ni = 0; ni < 8; ni++) {
            int d = ni * 8 + c0;
#pragma unroll
            for (int half = 0; half < 2; half++) {
                int i = wid * 16 + r0 + half * 8;
                if (i < SEQ) {
                    size_t dst = ((size_t)b * SEQ + i) * EMB + h * HDIM + d;
                    *reinterpret_cast<__half2*>(&att[dst]) =
                        __floats2half2_rn(acc[ni][half * 2 + 0], acc[ni][half * 2 + 1]);
                }
            }
        }
    }
}

// ---------------- launch ----------------
extern "C" void kernel_launch(void* const* d_in, const int* in_sizes, int n_in,
                              void* d_out, int out_size) {
    const float* x   = (const float*)d_in[0];
    const float* Wq  = (const float*)d_in[1];
    const float* bq  = (const float*)d_in[2];
    const float* Wk  = (const float*)d_in[3];
    const float* bk  = (const float*)d_in[4];
    const float* Wv  = (const float*)d_in[5];
    const float* bv  = (const float*)d_in[6];
    const float* Wo  = (const float*)d_in[7];
    const float* bo  = (const float*)d_in[8];
    const float* pos = (const float*)d_in[9];

    float* out = (float*)d_out;
    const size_t out_elems = (size_t)BATCH * EMB * SEQ;
    float* attn_out = ((size_t)out_size > out_elems) ? out + out_elems : nullptr;

    __half *xf, *wt, *att, *q, *k, *v;
    cudaGetSymbolAddress((void**)&xf,  g_xf);
    cudaGetSymbolAddress((void**)&wt,  g_wt);
    cudaGetSymbolAddress((void**)&q,   g_q);
    cudaGetSymbolAddress((void**)&k,   g_k);
    cudaGetSymbolAddress((void**)&v,   g_v);
    cudaGetSymbolAddress((void**)&att, g_att);

    cudaFuncSetAttribute(gemm_tc<0>, cudaFuncAttributeMaxDynamicSharedMemorySize, GEMM_SMEM);
    cudaFuncSetAttribute(gemm_tc<1>, cudaFuncAttributeMaxDynamicSharedMemorySize, GEMM_SMEM);
    cudaFuncSetAttribute(attention_kernel, cudaFuncAttributeMaxDynamicSharedMemorySize, ATT_SMEM);

    const size_t WSTRIDE = (size_t)EMB * EMB;

    // 1) weight transpose to K-major fp16
    {
        dim3 grid(EMB / 32, EMB / 32);
        dim3 blk(32, 32);
        wconvert_kernel<<<grid, blk>>>(Wq, wt + 0 * WSTRIDE);
        wconvert_kernel<<<grid, blk>>>(Wk, wt + 1 * WSTRIDE);
        wconvert_kernel<<<grid, blk>>>(Wv, wt + 2 * WSTRIDE);
        wconvert_kernel<<<grid, blk>>>(Wo, wt + 3 * WSTRIDE);
    }

    // 2) transpose + pos -> fp16
    {
        dim3 grid((SEQ + 31) / 32, EMB / 32, BATCH);
        dim3 blk(32, 32);
        transpose_pos_kernel<<<grid, blk>>>(x, pos, xf);
    }

    // 3) fused Q/K/V projection (one GEMM over N=3072)
    {
        dim3 grid(3 * EMB / BN, MROWS / BM);   // (24, 200)
        gemm_tc<0><<<grid, GEMM_THREADS, GEMM_SMEM>>>(
            xf, wt, bq, bk, bv, q, k, v);
    }

    // 4) attention (tensor cores)
    attention_kernel<<<BATCH * NHEAD, 256, ATT_SMEM>>>(q, k, v, att, attn_out);

    // 5) output projection (+ transpose back to [B, E, H, W])
    {
        dim3 grid(EMB / BN, MROWS / BM);
        gemm_tc<1><<<grid, GEMM_THREADS, GEMM_SMEM>>>(
            att, wt + 3 * WSTRIDE, bo, nullptr, nullptr, out, nullptr, nullptr);
    }
}